// round 7
// baseline (speedup 1.0000x reference)
#include <cuda_runtime.h>
#include <cuda_bf16.h>

#define BB   8
#define NPT  2048
#define KNN  16
#define H    128
#define LL   4
#define CDIM 128
#define EPS  1e-12f
#define P    8
#define NG   (BB * NPT / P)     // 2048 groups of 8 points
#define GSZ  (3 * H * P)        // 3072 floats per group, layout [d][c][p]

union F2 { float2 f; unsigned long long u; };

#define FMA2(acc, a, b)   asm("fma.rn.f32x2 %0, %1, %2, %0;" : "+l"(acc) : "l"(a), "l"(b))
#define MUL2(d, a, b)     asm("mul.rn.f32x2 %0, %1, %2;"     : "=l"(d)   : "l"(a), "l"(b))
#define ADD2(acc, a)      asm("add.rn.f32x2 %0, %1, %0;"     : "+l"(acc) : "l"(a))
#define PACKF2(d, lo, hi) asm("mov.b64 %0, {%1, %2};"        : "=l"(d)   : "f"(lo), "f"(hi))

// ---------------- scratch (static device globals; no runtime alloc) --------
__device__ __align__(16) float g_bufA[NG * GSZ];
__device__ __align__(16) float g_bufB[NG * GSZ];
__device__ int   g_idx[BB * NPT * KNN];
__device__ float g_g [BB * 3 * H];
__device__ float g_gp[BB * 3 * H];

// ---------------- helpers --------------------------------------------------
__device__ __forceinline__ void vact(float v0, float v1, float v2,
                                     float k0, float k1, float k2,
                                     float& r0, float& r1, float& r2) {
    float kn  = sqrtf(k0 * k0 + k1 * k1 + k2 * k2);
    float inv = 1.0f / fmaxf(kn, EPS);
    float a = k0 * inv, b = k1 * inv, c = k2 * inv;
    float dot = v0 * a + v1 * b + v2 * c;
    float s = fminf(dot, 0.0f);
    r0 = v0 - s * a; r1 = v1 - s * b; r2 = v2 - s * c;
}

// matvec over H channels, this thread-group's 4 points (2 f32x2 pairs), 3 dims.
// v layout [d][c][P]; qoff = 4*tg selects which half of the 8 points.
__device__ __forceinline__ void matvec4(const float* __restrict__ v,
                                        const float* __restrict__ wrow,
                                        F2 acc[3][2], int qoff) {
    const float4* w4p = (const float4*)wrow;
#pragma unroll 4
    for (int c4 = 0; c4 < 32; ++c4) {
        float4 w4 = w4p[c4];
        unsigned long long wp[4];
        PACKF2(wp[0], w4.x, w4.x);
        PACKF2(wp[1], w4.y, w4.y);
        PACKF2(wp[2], w4.z, w4.z);
        PACKF2(wp[3], w4.w, w4.w);
#pragma unroll
        for (int j = 0; j < 4; ++j) {
            int c = c4 * 4 + j;
#pragma unroll
            for (int d = 0; d < 3; ++d) {
                ulonglong2 va = *(const ulonglong2*)(v + (d * H + c) * P + qoff);
                FMA2(acc[d][0].u, wp[j], va.x);
                FMA2(acc[d][1].u, wp[j], va.y);
            }
        }
    }
}

// channel-equivariant normalize, this thread-group's 2 pairs.
// redu: [8 warps][2 pairs]. tg's warps are tg*4 .. tg*4+3.
__device__ __forceinline__ void cnorm4(F2 acc[3][2],
                                       unsigned long long (*redu)[2],
                                       int lane, int warp, int tg) {
    F2 nsq[2];
#pragma unroll
    for (int q = 0; q < 2; ++q) {
        MUL2(nsq[q].u, acc[0][q].u, acc[0][q].u);
        FMA2(nsq[q].u, acc[1][q].u, acc[1][q].u);
        FMA2(nsq[q].u, acc[2][q].u, acc[2][q].u);
    }
#pragma unroll
    for (int q = 0; q < 2; ++q) {
        unsigned long long v = nsq[q].u;
#pragma unroll
        for (int o = 16; o > 0; o >>= 1) {
            unsigned long long s = __shfl_xor_sync(0xffffffffu, v, o);
            ADD2(v, s);
        }
        if (lane == 0) redu[warp][q] = v;
    }
    __syncthreads();
#pragma unroll
    for (int q = 0; q < 2; ++q) {
        F2 cs; cs.u = redu[tg * 4 + 0][q];
        ADD2(cs.u, redu[tg * 4 + 1][q]);
        ADD2(cs.u, redu[tg * 4 + 2][q]);
        ADD2(cs.u, redu[tg * 4 + 3][q]);
        float cnx = sqrtf(cs.f.x), cny = sqrtf(cs.f.y);
        float nx  = sqrtf(nsq[q].f.x), ny = sqrtf(nsq[q].f.y);
        float fx = (nx / fmaxf(nx, EPS)) / fmaxf(cnx, EPS);
        float fy = (ny / fmaxf(ny, EPS)) / fmaxf(cny, EPS);
        unsigned long long fp; PACKF2(fp, fx, fy);
#pragma unroll
        for (int d = 0; d < 3; ++d) MUL2(acc[d][q].u, acc[d][q].u, fp);
    }
}

// ---------------- kNN: register-resident branch-free top-16 ----------------
__global__ __launch_bounds__(128)
void knn_kernel(const float* __restrict__ x) {
    int b = blockIdx.y;
    int i = blockIdx.x * blockDim.x + threadIdx.x;
    __shared__ float px[NPT], py[NPT], pz[NPT], sq[NPT];
    const float* xb = x + b * 3 * NPT;
    for (int n = threadIdx.x; n < NPT; n += blockDim.x) {
        float a = xb[n], c = xb[NPT + n], e = xb[2 * NPT + n];
        px[n] = a; py[n] = c; pz[n] = e;
        sq[n] = a * a + c * c + e * e;
    }
    __syncthreads();
    float qx = px[i], qy = py[i], qz = pz[i], qs = sq[i];
    float bd[KNN]; int bi[KNN];
#pragma unroll
    for (int t = 0; t < KNN; ++t) { bd[t] = 3.4e38f; bi[t] = 0; }

#pragma unroll 4
    for (int j = 0; j < NPT; ++j) {
        float dot = qx * px[j] + qy * py[j] + qz * pz[j];
        float d2  = fmaf(-2.0f, dot, qs + sq[j]);
        if (d2 < bd[KNN - 1]) {
            float cd = d2; int ci = j;
#pragma unroll
            for (int t = 0; t < KNN; ++t) {
                bool lt = cd < bd[t];
                float nd = lt ? cd    : bd[t];
                int   ni = lt ? ci    : bi[t];
                float od = lt ? bd[t] : cd;
                int   oi = lt ? bi[t] : ci;
                bd[t] = nd; bi[t] = ni;
                cd = od; ci = oi;
            }
        }
    }
    int base = (b * NPT + i) * KNN;
#pragma unroll
    for (int t = 0; t < KNN; ++t) g_idx[base + t] = bi[t];
}

// ---------------- input stage: y -> vec_lna(W_in, Wd_in) -> mean over K ----
// 256 threads: h = tid&127, tg = tid>>7 owns k = 8*tg .. 8*tg+7.
// vsh layout: [d][c][k padded to 20]
__global__ __launch_bounds__(256)
void input_kernel(const float* __restrict__ x,
                  const float* __restrict__ Win,
                  const float* __restrict__ Wdin) {
    int pt = blockIdx.x;
    int b  = pt >> 11;
    int n  = pt & (NPT - 1);
    int tid = threadIdx.x;
    int h  = tid & 127;
    int tg = tid >> 7;
    int lane = tid & 31, warp = tid >> 5;

    __shared__ __align__(16) float vsh[3 * H * 20];
    __shared__ float ysh[3][3][KNN];
    __shared__ float red[8][8];          // [warp][k-local]
    __shared__ float psum[2][3 * H];

    const float* xb = x + b * 3 * NPT;
    if (tid < KNN) {
        float cx = xb[n], cy = xb[NPT + n], cz = xb[2 * NPT + n];
        int j = g_idx[pt * KNN + tid];
        float nx = xb[j], ny = xb[NPT + j], nz = xb[2 * NPT + j];
        float nn  = sqrtf(cx * cx + cy * cy + cz * cz);
        float inv = 1.0f / fmaxf(nn, EPS);
        float dx = cx * inv, dy = cy * inv, dz = cz * inv;
        ysh[0][0][tid] = dy * nz - dz * ny;
        ysh[0][1][tid] = dz * nx - dx * nz;
        ysh[0][2][tid] = dx * ny - dy * nx;
        ysh[1][0][tid] = nx - cx; ysh[1][1][tid] = ny - cy; ysh[1][2][tid] = nz - cz;
        ysh[2][0][tid] = cx;      ysh[2][1][tid] = cy;      ysh[2][2][tid] = cz;
    }
    __syncthreads();

    float w0 = Win[h * 3 + 0], w1 = Win[h * 3 + 1], w2 = Win[h * 3 + 2];
    int k0 = 8 * tg;
    float u[8][3];
    float nsq[8];
#pragma unroll
    for (int kk = 0; kk < 8; ++kk) {
        int k = k0 + kk;
        float s = 0.0f;
#pragma unroll
        for (int d = 0; d < 3; ++d) {
            float t = w0 * ysh[0][d][k] + w1 * ysh[1][d][k] + w2 * ysh[2][d][k];
            u[kk][d] = t; s += t * t;
        }
        nsq[kk] = s;
    }
    // channel-norm: sum nsq over h (4 warps per tg cover h=0..127)
#pragma unroll
    for (int kk = 0; kk < 8; ++kk) {
        float v = nsq[kk];
        for (int o = 16; o > 0; o >>= 1) v += __shfl_xor_sync(0xffffffffu, v, o);
        if (lane == 0) red[warp][kk] = v;
    }
    __syncthreads();
#pragma unroll
    for (int kk = 0; kk < 8; ++kk) {
        float cn = sqrtf(red[tg * 4 + 0][kk] + red[tg * 4 + 1][kk] +
                         red[tg * 4 + 2][kk] + red[tg * 4 + 3][kk]);
        float nr = sqrtf(nsq[kk]);
        float f  = (nr / fmaxf(nr, EPS)) / fmaxf(cn, EPS);
#pragma unroll
        for (int d = 0; d < 3; ++d) u[kk][d] *= f;
    }
    // write scaled v to vsh: 2 float4 per dim (its 8 k's, contiguous)
#pragma unroll
    for (int d = 0; d < 3; ++d) {
        float* vb = vsh + (d * H + h) * 20 + k0;
        *(float4*)(vb + 0) = make_float4(u[0][d], u[1][d], u[2][d], u[3][d]);
        *(float4*)(vb + 4) = make_float4(u[4][d], u[5][d], u[6][d], u[7][d]);
    }
    __syncthreads();

    // kvec = Wd_in @ v, packed f32x2 over this tg's 4 k-pairs
    F2 a[3][4];
#pragma unroll
    for (int d = 0; d < 3; ++d)
#pragma unroll
        for (int q = 0; q < 4; ++q) a[d][q].u = 0ull;

    const float4* wd4 = (const float4*)(Wdin + h * H);
#pragma unroll 4
    for (int c4 = 0; c4 < 32; ++c4) {
        float4 w4 = wd4[c4];
        unsigned long long wp[4];
        PACKF2(wp[0], w4.x, w4.x);
        PACKF2(wp[1], w4.y, w4.y);
        PACKF2(wp[2], w4.z, w4.z);
        PACKF2(wp[3], w4.w, w4.w);
#pragma unroll
        for (int j = 0; j < 4; ++j) {
            int c = c4 * 4 + j;
#pragma unroll
            for (int d = 0; d < 3; ++d) {
                const ulonglong2* vp = (const ulonglong2*)(vsh + (d * H + c) * 20 + k0);
                ulonglong2 v0 = vp[0], v1 = vp[1];
                FMA2(a[d][0].u, wp[j], v0.x); FMA2(a[d][1].u, wp[j], v0.y);
                FMA2(a[d][2].u, wp[j], v1.x); FMA2(a[d][3].u, wp[j], v1.y);
            }
        }
    }

    // vec_act + partial mean over this tg's 8 k's
    float a0 = 0.0f, a1 = 0.0f, a2 = 0.0f;
#pragma unroll
    for (int q = 0; q < 4; ++q) {
        float r0, r1, r2;
        vact(u[2 * q][0], u[2 * q][1], u[2 * q][2],
             a[0][q].f.x, a[1][q].f.x, a[2][q].f.x, r0, r1, r2);
        a0 += r0; a1 += r1; a2 += r2;
        vact(u[2 * q + 1][0], u[2 * q + 1][1], u[2 * q + 1][2],
             a[0][q].f.y, a[1][q].f.y, a[2][q].f.y, r0, r1, r2);
        a0 += r0; a1 += r1; a2 += r2;
    }
    psum[tg][0 * H + h] = a0;
    psum[tg][1 * H + h] = a1;
    psum[tg][2 * H + h] = a2;
    __syncthreads();

    if (tg == 0) {
        int grp = pt >> 3, p = pt & 7;
        float* ob = g_bufA + grp * GSZ + p;
#pragma unroll
        for (int d = 0; d < 3; ++d)
            ob[(d * H + h) * P] = (psum[0][d * H + h] + psum[1][d * H + h]) * (1.0f / KNN);
    }
}

// ---------------- per-point vec_lna: bufA -> bufB --------------------------
__global__ __launch_bounds__(256)
void lna_kernel(const float* __restrict__ W, const float* __restrict__ Wd) {
    int grp = blockIdx.x;
    int tid = threadIdx.x;
    int h = tid & 127, tg = tid >> 7;
    int lane = tid & 31, warp = tid >> 5;
    int qoff = 4 * tg;
    __shared__ __align__(16) float ish[GSZ];
    __shared__ __align__(16) float vsh[GSZ];
    __shared__ unsigned long long redu[8][2];

    const float4* s4 = (const float4*)(g_bufA + grp * GSZ);
    float4* i4 = (float4*)ish;
#pragma unroll
    for (int t = 0; t < 3; ++t) i4[t * 256 + tid] = s4[t * 256 + tid];
    __syncthreads();

    F2 acc[3][2];
#pragma unroll
    for (int d = 0; d < 3; ++d) { acc[d][0].u = 0ull; acc[d][1].u = 0ull; }
    matvec4(ish, W + h * H, acc, qoff);
    cnorm4(acc, redu, lane, warp, tg);

#pragma unroll
    for (int d = 0; d < 3; ++d)
        *(ulonglong2*)(vsh + (d * H + h) * P + qoff) =
            make_ulonglong2(acc[d][0].u, acc[d][1].u);
    __syncthreads();

    F2 kv[3][2];
#pragma unroll
    for (int d = 0; d < 3; ++d) { kv[d][0].u = 0ull; kv[d][1].u = 0ull; }
    matvec4(vsh, Wd + h * H, kv, qoff);

    float* dst = g_bufB + grp * GSZ;
#pragma unroll
    for (int q = 0; q < 2; ++q) {
        float r0x, r1x, r2x, r0y, r1y, r2y;
        vact(acc[0][q].f.x, acc[1][q].f.x, acc[2][q].f.x,
             kv[0][q].f.x,  kv[1][q].f.x,  kv[2][q].f.x, r0x, r1x, r2x);
        vact(acc[0][q].f.y, acc[1][q].f.y, acc[2][q].f.y,
             kv[0][q].f.y,  kv[1][q].f.y,  kv[2][q].f.y, r0y, r1y, r2y);
        F2 t0, t1, t2;
        t0.f = make_float2(r0x, r0y); t1.f = make_float2(r1x, r1y); t2.f = make_float2(r2x, r2y);
        acc[0][q] = t0; acc[1][q] = t1; acc[2][q] = t2;
    }
#pragma unroll
    for (int d = 0; d < 3; ++d)
        *(ulonglong2*)(dst + (d * H + h) * P + qoff) =
            make_ulonglong2(acc[d][0].u, acc[d][1].u);
}

// ---------------- global mean over N of bufB -> g_g ------------------------
__global__ void mean_kernel() {
    int fl = blockIdx.x;                 // b*384 + c, c = d*128 + h
    int b = fl / (3 * H), c = fl % (3 * H);
    const float* base = g_bufB + (size_t)b * (NPT / P) * GSZ + c * P;
    float s = 0.0f;
    for (int i = threadIdx.x; i < 2 * (NPT / P); i += 128) {
        int g = i >> 1, q = i & 1;
        float4 v = *(const float4*)(base + g * GSZ + q * 4);
        s += (v.x + v.y) + (v.z + v.w);
    }
    __shared__ float rs[4];
    for (int o = 16; o > 0; o >>= 1) s += __shfl_xor_sync(0xffffffffu, s, o);
    if ((threadIdx.x & 31) == 0) rs[threadIdx.x >> 5] = s;
    __syncthreads();
    if (threadIdx.x == 0)
        g_g[fl] = (rs[0] + rs[1] + rs[2] + rs[3]) * (1.0f / NPT);
}

// ---------------- gpart = Gs[:, H:2H] @ g per batch ------------------------
__global__ void gpart_kernel(const float* __restrict__ Gi) {
    int b = blockIdx.x;
    int t = threadIdx.x;                 // 384 threads: t = d*128 + h
    __shared__ float gs[3 * H];
    gs[t] = g_g[b * 3 * H + t];
    __syncthreads();
    int d = t >> 7, h = t & 127;
    const float4* w4p = (const float4*)(Gi + h * (2 * H) + H);
    const float4* g4p = (const float4*)&gs[d * H];
    float s = 0.0f;
#pragma unroll
    for (int c = 0; c < H / 4; ++c) {
        float4 w = w4p[c], v = g4p[c];
        s += w.x * v.x + w.y * v.y + w.z * v.z + w.w * v.w;
    }
    g_gp[b * 3 * H + t] = s;
}

// -------- G-layer: vec_lna([h,g], Gs, Gds) + W_out accumulation ------------
__global__ __launch_bounds__(256)
void glayer_kernel(const float* __restrict__ Gl, const float* __restrict__ Gd,
                   const float* __restrict__ Wout, float* __restrict__ obig,
                   int layer) {
    int grp = blockIdx.x;
    int b = grp >> 8;
    int tid = threadIdx.x;
    int h = tid & 127, tg = tid >> 7;
    int lane = tid & 31, warp = tid >> 5;
    int qoff = 4 * tg;
    __shared__ __align__(16) float ish[GSZ];
    __shared__ __align__(16) float vsh[GSZ];
    __shared__ unsigned long long redu[8][2];

    const float4* s4 = (const float4*)(g_bufB + grp * GSZ);
    float4* i4 = (float4*)ish;
#pragma unroll
    for (int t = 0; t < 3; ++t) i4[t * 256 + tid] = s4[t * 256 + tid];
    __syncthreads();

    F2 acc[3][2];
#pragma unroll
    for (int d = 0; d < 3; ++d) {
        float gv = g_gp[b * 3 * H + d * H + h];
        unsigned long long gp; PACKF2(gp, gv, gv);
        acc[d][0].u = gp; acc[d][1].u = gp;
    }
    matvec4(ish, Gl + h * (2 * H), acc, qoff);
    cnorm4(acc, redu, lane, warp, tg);

#pragma unroll
    for (int d = 0; d < 3; ++d)
        *(ulonglong2*)(vsh + (d * H + h) * P + qoff) =
            make_ulonglong2(acc[d][0].u, acc[d][1].u);
    __syncthreads();

    F2 kv[3][2];
#pragma unroll
    for (int d = 0; d < 3; ++d) { kv[d][0].u = 0ull; kv[d][1].u = 0ull; }
    matvec4(vsh, Gd + h * H, kv, qoff);

    float* dst = g_bufA + grp * GSZ;
#pragma unroll
    for (int q = 0; q < 2; ++q) {
        float r0x, r1x, r2x, r0y, r1y, r2y;
        vact(acc[0][q].f.x, acc[1][q].f.x, acc[2][q].f.x,
             kv[0][q].f.x,  kv[1][q].f.x,  kv[2][q].f.x, r0x, r1x, r2x);
        vact(acc[0][q].f.y, acc[1][q].f.y, acc[2][q].f.y,
             kv[0][q].f.y,  kv[1][q].f.y,  kv[2][q].f.y, r0y, r1y, r2y);
        F2 t0, t1, t2;
        t0.f = make_float2(r0x, r0y); t1.f = make_float2(r1x, r1y); t2.f = make_float2(r2x, r2y);
        acc[0][q] = t0; acc[1][q] = t1; acc[2][q] = t2;
    }
#pragma unroll
    for (int d = 0; d < 3; ++d) {
        ulonglong2 v = make_ulonglong2(acc[d][0].u, acc[d][1].u);
        *(ulonglong2*)(dst + (d * H + h) * P + qoff) = v;
        *(ulonglong2*)(ish + (d * H + h) * P + qoff) = v;
    }
    __syncthreads();

    // W_out slice for this layer (thread h = output channel cd)
    F2 o[3][2];
#pragma unroll
    for (int d = 0; d < 3; ++d) { o[d][0].u = 0ull; o[d][1].u = 0ull; }
    matvec4(ish, Wout + h * (LL * H) + layer * H, o, qoff);

    int n0 = (grp & 255) * P;
#pragma unroll
    for (int d = 0; d < 3; ++d) {
        ulonglong2* dp = (ulonglong2*)(obig + ((b * CDIM + h) * 3 + d) * NPT + n0 + qoff);
        if (layer == 0) {
            *dp = make_ulonglong2(o[d][0].u, o[d][1].u);
        } else {
            ulonglong2 e = *dp;
            ADD2(o[d][0].u, e.x); ADD2(o[d][1].u, e.y);
            *dp = make_ulonglong2(o[d][0].u, o[d][1].u);
        }
    }
}

// ---------------- final mean over N of the big output ----------------------
__global__ void outmean_kernel(const float* __restrict__ obig,
                               float* __restrict__ om) {
    int r = blockIdx.x;                  // (b*CD + cd)*3 + d
    float s = 0.0f;
    for (int n = threadIdx.x; n < NPT; n += blockDim.x)
        s += obig[r * NPT + n];
    __shared__ float rs[8];
    for (int o = 16; o > 0; o >>= 1) s += __shfl_xor_sync(0xffffffffu, s, o);
    if ((threadIdx.x & 31) == 0) rs[threadIdx.x >> 5] = s;
    __syncthreads();
    if (threadIdx.x == 0) {
        float t = 0.0f;
#pragma unroll
        for (int w = 0; w < 8; ++w) t += rs[w];
        om[r] = t * (1.0f / NPT);
    }
}

// ---------------------------------------------------------------------------
extern "C" void kernel_launch(void* const* d_in, const int* in_sizes, int n_in,
                              void* d_out, int out_size) {
    const float* x    = (const float*)d_in[0];
    const float* Win  = (const float*)d_in[1];
    const float* Wdin = (const float*)d_in[2];
    const float* Ws   = (const float*)d_in[3];
    const float* Wds  = (const float*)d_in[4];
    const float* Gs   = (const float*)d_in[5];
    const float* Gds  = (const float*)d_in[6];
    const float* Wout = (const float*)d_in[7];
    (void)in_sizes; (void)n_in; (void)out_size;

    float* out  = (float*)d_out;
    float* om   = out;                    // (B, CD, 3) mean
    float* obig = out + BB * CDIM * 3;    // (B, CD, 3, N)

    knn_kernel<<<dim3(NPT / 128, BB), 128>>>(x);
    input_kernel<<<BB * NPT, 256>>>(x, Win, Wdin);

    for (int i = 0; i < LL; ++i) {
        lna_kernel<<<NG, 256>>>(Ws + i * H * H, Wds + i * H * H);
        mean_kernel<<<BB * 3 * H, 128>>>();
        gpart_kernel<<<BB, 3 * H>>>(Gs + i * H * 2 * H);
        glayer_kernel<<<NG, 256>>>(Gs + i * H * 2 * H,
                                   Gds + i * H * H,
                                   Wout, obig, i);
    }
    outmean_kernel<<<BB * CDIM * 3, 256>>>(obig, om);
}

// round 11
// speedup vs baseline: 1.4745x; 1.4745x over previous
#include <cuda_runtime.h>
#include <cuda_bf16.h>

#define BB   8
#define NPT  2048
#define KNN  16
#define H    128
#define LL   4
#define CDIM 128
#define EPS  1e-12f
#define TBLK 32                       // points per tc block
#define NBLK (BB * NPT / TBLK)        // 512 tc blocks
#define BLKF (3 * H * TBLK)           // 12288 floats per block tile [d][c][p32]

// ---------------- scratch (static device globals; no runtime alloc) --------
__device__ __align__(16) float g_bufA[NBLK * BLKF];
__device__ __align__(16) float g_bufB[NBLK * BLKF];
__device__ int   g_idx[BB * NPT * KNN];
__device__ float g_g [BB * 3 * H];
__device__ float g_gp[BB * 3 * H];

// ---------------- helpers --------------------------------------------------
__device__ __forceinline__ unsigned tf32r(float f) {
    unsigned u; asm("cvt.rna.tf32.f32 %0, %1;" : "=r"(u) : "f"(f)); return u;
}
__device__ __forceinline__ float tf32f(float f) { return __uint_as_float(tf32r(f)); }
// hi/lo split for 3xTF32: v ~= hi + lo, each tf32-representable
__device__ __forceinline__ float2 split32(float v) {
    float hi = tf32f(v);
    float lo = tf32f(v - hi);
    return make_float2(hi, lo);
}

__device__ __forceinline__ void mma8(float* c, const unsigned* a,
                                     unsigned b0, unsigned b1) {
    asm volatile(
        "mma.sync.aligned.m16n8k8.row.col.f32.tf32.tf32.f32 "
        "{%0,%1,%2,%3}, {%4,%5,%6,%7}, {%8,%9}, {%0,%1,%2,%3};"
        : "+f"(c[0]), "+f"(c[1]), "+f"(c[2]), "+f"(c[3])
        : "r"(a[0]), "r"(a[1]), "r"(a[2]), "r"(a[3]), "r"(b0), "r"(b1));
}

__device__ __forceinline__ void vact(float v0, float v1, float v2,
                                     float k0, float k1, float k2,
                                     float& r0, float& r1, float& r2) {
    float kn  = sqrtf(k0 * k0 + k1 * k1 + k2 * k2);
    float inv = 1.0f / fmaxf(kn, EPS);
    float a = k0 * inv, b = k1 * inv, c = k2 * inv;
    float dot = v0 * a + v1 * b + v2 * c;
    float s = fminf(dot, 0.0f);
    r0 = v0 - s * a; r1 = v1 - s * b; r2 = v2 - s * c;
}

// 3xTF32 GEMM: C[128h x 96col] = A[128x128] * act[128c x 96col], col = d*32+p.
// buf slots are float2 {hi,lo}, slot index = row*32 + (p ^ ((row&3)<<3)).
// Warp w owns rows 32w..32w+31; lane -> q = lane&3, r = lane>>2.
__device__ __forceinline__ void gemm3_tc(const float* __restrict__ A, int ws,
                                         const float* __restrict__ buf,
                                         float c[2][12][4], int w, int q, int r) {
    const float* a0p = A + (32 * w + r) * ws;
    const float* a1p = a0p + 8 * ws;
    const float* a2p = a0p + 16 * ws;
    const float* a3p = a0p + 24 * ws;
    int swz = q << 3;
#pragma unroll 2
    for (int k8 = 0; k8 < 16; ++k8) {
        int kb = k8 * 8;
        float af[2][4];
        af[0][0] = a0p[kb + q];     af[0][1] = a1p[kb + q];
        af[0][2] = a0p[kb + q + 4]; af[0][3] = a1p[kb + q + 4];
        af[1][0] = a2p[kb + q];     af[1][1] = a3p[kb + q];
        af[1][2] = a2p[kb + q + 4]; af[1][3] = a3p[kb + q + 4];
        unsigned ah[2][4], al[2][4];
#pragma unroll
        for (int mt = 0; mt < 2; ++mt)
#pragma unroll
            for (int t = 0; t < 4; ++t) {
                ah[mt][t] = tf32r(af[mt][t]);
                al[mt][t] = tf32r(af[mt][t] - __uint_as_float(ah[mt][t]));
            }
#pragma unroll
        for (int jn = 0; jn < 12; ++jn) {
            int d = jn >> 2;
            int boff = (((jn & 3) * 8) ^ swz) + r;
            float2 b0 = *(const float2*)(buf + ((d * 128 + kb + q) * 32 + boff) * 2);
            float2 b1 = *(const float2*)(buf + ((d * 128 + kb + q + 4) * 32 + boff) * 2);
            unsigned bh0 = __float_as_uint(b0.x), bl0 = __float_as_uint(b0.y);
            unsigned bh1 = __float_as_uint(b1.x), bl1 = __float_as_uint(b1.y);
            mma8(c[0][jn], ah[0], bh0, bh1);
            mma8(c[1][jn], ah[1], bh0, bh1);
            mma8(c[0][jn], ah[0], bl0, bl1);
            mma8(c[1][jn], ah[1], bl0, bl1);
            mma8(c[0][jn], al[0], bh0, bh1);
            mma8(c[1][jn], al[1], bh0, bh1);
        }
    }
}

// ---------------- kNN: register-resident branch-free top-16 ----------------
__global__ __launch_bounds__(128)
void knn_kernel(const float* __restrict__ x) {
    int b = blockIdx.y;
    int i = blockIdx.x * blockDim.x + threadIdx.x;
    __shared__ float px[NPT], py[NPT], pz[NPT], sq[NPT];
    const float* xb = x + b * 3 * NPT;
    for (int n = threadIdx.x; n < NPT; n += blockDim.x) {
        float a = xb[n], c = xb[NPT + n], e = xb[2 * NPT + n];
        px[n] = a; py[n] = c; pz[n] = e;
        sq[n] = a * a + c * c + e * e;
    }
    __syncthreads();
    float qx = px[i], qy = py[i], qz = pz[i], qs = sq[i];
    float bd[KNN]; int bi[KNN];
#pragma unroll
    for (int t = 0; t < KNN; ++t) { bd[t] = 3.4e38f; bi[t] = 0; }
#pragma unroll 4
    for (int j = 0; j < NPT; ++j) {
        float dot = qx * px[j] + qy * py[j] + qz * pz[j];
        float d2  = fmaf(-2.0f, dot, qs + sq[j]);
        if (d2 < bd[KNN - 1]) {
            float cd = d2; int ci = j;
#pragma unroll
            for (int t = 0; t < KNN; ++t) {
                bool lt = cd < bd[t];
                float nd = lt ? cd    : bd[t];
                int   ni = lt ? ci    : bi[t];
                float od = lt ? bd[t] : cd;
                int   oi = lt ? bi[t] : ci;
                bd[t] = nd; bi[t] = ni;
                cd = od; ci = oi;
            }
        }
    }
    int base = (b * NPT + i) * KNN;
#pragma unroll
    for (int t = 0; t < KNN; ++t) g_idx[base + t] = bi[t];
}

// ---------------- input stage (FFMA2 path, exact fp32) ----------------------
union F2 { float2 f; unsigned long long u; };
#define FMA2(acc, a, b)   asm("fma.rn.f32x2 %0, %1, %2, %0;" : "+l"(acc) : "l"(a), "l"(b))
#define PACKF2(d, lo, hi) asm("mov.b64 %0, {%1, %2};"        : "=l"(d)   : "f"(lo), "f"(hi))

__global__ __launch_bounds__(256)
void input_kernel(const float* __restrict__ x,
                  const float* __restrict__ Win,
                  const float* __restrict__ Wdin) {
    int pt = blockIdx.x;
    int b  = pt >> 11;
    int n  = pt & (NPT - 1);
    int tid = threadIdx.x;
    int h  = tid & 127;
    int tg = tid >> 7;
    int lane = tid & 31, warp = tid >> 5;

    __shared__ __align__(16) float vsh[3 * H * 20];
    __shared__ float ysh[3][3][KNN];
    __shared__ float red[8][8];
    __shared__ float psum[2][3 * H];

    const float* xb = x + b * 3 * NPT;
    if (tid < KNN) {
        float cx = xb[n], cy = xb[NPT + n], cz = xb[2 * NPT + n];
        int j = g_idx[pt * KNN + tid];
        float nx = xb[j], ny = xb[NPT + j], nz = xb[2 * NPT + j];
        float nn  = sqrtf(cx * cx + cy * cy + cz * cz);
        float inv = 1.0f / fmaxf(nn, EPS);
        float dx = cx * inv, dy = cy * inv, dz = cz * inv;
        ysh[0][0][tid] = dy * nz - dz * ny;
        ysh[0][1][tid] = dz * nx - dx * nz;
        ysh[0][2][tid] = dx * ny - dy * nx;
        ysh[1][0][tid] = nx - cx; ysh[1][1][tid] = ny - cy; ysh[1][2][tid] = nz - cz;
        ysh[2][0][tid] = cx;      ysh[2][1][tid] = cy;      ysh[2][2][tid] = cz;
    }
    __syncthreads();

    float w0 = Win[h * 3 + 0], w1 = Win[h * 3 + 1], w2 = Win[h * 3 + 2];
    int k0 = 8 * tg;
    float u[8][3];
    float nsq[8];
#pragma unroll
    for (int kk = 0; kk < 8; ++kk) {
        int k = k0 + kk;
        float s = 0.0f;
#pragma unroll
        for (int d = 0; d < 3; ++d) {
            float t = w0 * ysh[0][d][k] + w1 * ysh[1][d][k] + w2 * ysh[2][d][k];
            u[kk][d] = t; s += t * t;
        }
        nsq[kk] = s;
    }
#pragma unroll
    for (int kk = 0; kk < 8; ++kk) {
        float v = nsq[kk];
        for (int o = 16; o > 0; o >>= 1) v += __shfl_xor_sync(0xffffffffu, v, o);
        if (lane == 0) red[warp][kk] = v;
    }
    __syncthreads();
#pragma unroll
    for (int kk = 0; kk < 8; ++kk) {
        float cn = sqrtf(red[tg * 4 + 0][kk] + red[tg * 4 + 1][kk] +
                         red[tg * 4 + 2][kk] + red[tg * 4 + 3][kk]);
        float nr = sqrtf(nsq[kk]);
        float f  = (nr / fmaxf(nr, EPS)) / fmaxf(cn, EPS);
#pragma unroll
        for (int d = 0; d < 3; ++d) u[kk][d] *= f;
    }
#pragma unroll
    for (int d = 0; d < 3; ++d) {
        float* vb = vsh + (d * H + h) * 20 + k0;
        *(float4*)(vb + 0) = make_float4(u[0][d], u[1][d], u[2][d], u[3][d]);
        *(float4*)(vb + 4) = make_float4(u[4][d], u[5][d], u[6][d], u[7][d]);
    }
    __syncthreads();

    F2 a[3][4];
#pragma unroll
    for (int d = 0; d < 3; ++d)
#pragma unroll
        for (int q = 0; q < 4; ++q) a[d][q].u = 0ull;

    const float4* wd4 = (const float4*)(Wdin + h * H);
#pragma unroll 4
    for (int c4 = 0; c4 < 32; ++c4) {
        float4 w4 = wd4[c4];
        unsigned long long wp[4];
        PACKF2(wp[0], w4.x, w4.x);
        PACKF2(wp[1], w4.y, w4.y);
        PACKF2(wp[2], w4.z, w4.z);
        PACKF2(wp[3], w4.w, w4.w);
#pragma unroll
        for (int j = 0; j < 4; ++j) {
            int c = c4 * 4 + j;
#pragma unroll
            for (int d = 0; d < 3; ++d) {
                const ulonglong2* vp = (const ulonglong2*)(vsh + (d * H + c) * 20 + k0);
                ulonglong2 v0 = vp[0], v1 = vp[1];
                FMA2(a[d][0].u, wp[j], v0.x); FMA2(a[d][1].u, wp[j], v0.y);
                FMA2(a[d][2].u, wp[j], v1.x); FMA2(a[d][3].u, wp[j], v1.y);
            }
        }
    }

    float a0 = 0.0f, a1 = 0.0f, a2 = 0.0f;
#pragma unroll
    for (int q = 0; q < 4; ++q) {
        float r0, r1, r2;
        vact(u[2 * q][0], u[2 * q][1], u[2 * q][2],
             a[0][q].f.x, a[1][q].f.x, a[2][q].f.x, r0, r1, r2);
        a0 += r0; a1 += r1; a2 += r2;
        vact(u[2 * q + 1][0], u[2 * q + 1][1], u[2 * q + 1][2],
             a[0][q].f.y, a[1][q].f.y, a[2][q].f.y, r0, r1, r2);
        a0 += r0; a1 += r1; a2 += r2;
    }
    psum[tg][0 * H + h] = a0;
    psum[tg][1 * H + h] = a1;
    psum[tg][2 * H + h] = a2;
    __syncthreads();

    if (tg == 0) {
        int blk = pt >> 5, p = pt & 31;
        float* ob = g_bufA + blk * BLKF + p;
#pragma unroll
        for (int d = 0; d < 3; ++d)
            ob[(d * H + h) * 32] =
                (psum[0][d * H + h] + psum[1][d * H + h]) * (1.0f / KNN);
    }
}

// ---------------- lna via 3xTF32 tensor cores: bufA -> bufB -----------------
__global__ __launch_bounds__(128)
void lna_tc(const float* __restrict__ W, const float* __restrict__ Wd) {
    extern __shared__ float buf[];       // float2 hi/lo slots, 96 KB
    __shared__ float red[4][32];
    int tid = threadIdx.x;
    int w = tid >> 5, lane = tid & 31, q = lane & 3, r = lane >> 2;
    int blk = blockIdx.x;

    const float4* gsrc = (const float4*)(g_bufA + blk * BLKF);
#pragma unroll 4
    for (int i = tid; i < 3072; i += 128) {
        float4 v = gsrc[i];
        int row = i >> 3, pw = (i & 7) << 2;
        float2* ds = (float2*)buf + row * 32 + (pw ^ ((row & 3) << 3));
        ds[0] = split32(v.x); ds[1] = split32(v.y);
        ds[2] = split32(v.z); ds[3] = split32(v.w);
    }
    __syncthreads();

    float c1[2][12][4];
#pragma unroll
    for (int mt = 0; mt < 2; ++mt)
#pragma unroll
        for (int jn = 0; jn < 12; ++jn)
#pragma unroll
            for (int cr = 0; cr < 4; ++cr) c1[mt][jn][cr] = 0.0f;
    gemm3_tc(W, 128, buf, c1, w, q, r);

    // channel-equivariant norm
    float n2[2][4][4];
#pragma unroll
    for (int mt = 0; mt < 2; ++mt)
#pragma unroll
        for (int jj = 0; jj < 4; ++jj)
#pragma unroll
            for (int cr = 0; cr < 4; ++cr)
                n2[mt][jj][cr] = c1[mt][jj][cr] * c1[mt][jj][cr]
                               + c1[mt][4 + jj][cr] * c1[mt][4 + jj][cr]
                               + c1[mt][8 + jj][cr] * c1[mt][8 + jj][cr];
    float lcn[4][2];
#pragma unroll
    for (int jj = 0; jj < 4; ++jj)
#pragma unroll
        for (int e = 0; e < 2; ++e)
            lcn[jj][e] = n2[0][jj][e] + n2[0][jj][e + 2]
                       + n2[1][jj][e] + n2[1][jj][e + 2];
#pragma unroll
    for (int o = 4; o < 32; o <<= 1)
#pragma unroll
        for (int jj = 0; jj < 4; ++jj)
#pragma unroll
            for (int e = 0; e < 2; ++e)
                lcn[jj][e] += __shfl_xor_sync(0xffffffffu, lcn[jj][e], o);
    if (r == 0)
#pragma unroll
        for (int jj = 0; jj < 4; ++jj)
#pragma unroll
            for (int e = 0; e < 2; ++e)
                red[w][jj * 8 + 2 * q + e] = lcn[jj][e];
    __syncthreads();

    float cns[4][2];
#pragma unroll
    for (int jj = 0; jj < 4; ++jj)
#pragma unroll
        for (int e = 0; e < 2; ++e) {
            int col = jj * 8 + 2 * q + e;
            cns[jj][e] = sqrtf(red[0][col] + red[1][col] + red[2][col] + red[3][col]);
        }

    // scale + store v' (hi/lo) back into buf
#pragma unroll
    for (int mt = 0; mt < 2; ++mt)
#pragma unroll
        for (int rh = 0; rh < 2; ++rh)
#pragma unroll
            for (int jj = 0; jj < 4; ++jj) {
                int ch = 32 * w + 16 * mt + 8 * rh + r;
                int ps = (jj * 8 + 2 * q) ^ ((ch & 3) << 3);
                float nA = sqrtf(n2[mt][jj][rh * 2]);
                float nB = sqrtf(n2[mt][jj][rh * 2 + 1]);
                float f0 = (nA / fmaxf(nA, EPS)) / fmaxf(cns[jj][0], EPS);
                float f1 = (nB / fmaxf(nB, EPS)) / fmaxf(cns[jj][1], EPS);
#pragma unroll
                for (int d = 0; d < 3; ++d) {
                    float2 s0 = split32(c1[mt][4 * d + jj][rh * 2] * f0);
                    float2 s1 = split32(c1[mt][4 * d + jj][rh * 2 + 1] * f1);
                    *(float4*)((float2*)buf + (d * 128 + ch) * 32 + ps) =
                        make_float4(s0.x, s0.y, s1.x, s1.y);
                }
            }
    __syncthreads();

    float c2[2][12][4];
#pragma unroll
    for (int mt = 0; mt < 2; ++mt)
#pragma unroll
        for (int jn = 0; jn < 12; ++jn)
#pragma unroll
            for (int cr = 0; cr < 4; ++cr) c2[mt][jn][cr] = 0.0f;
    gemm3_tc(Wd, 128, buf, c2, w, q, r);

    // vact + store to g_bufB (plain fp32 layout)
    float* gdst = g_bufB + blk * BLKF;
#pragma unroll
    for (int mt = 0; mt < 2; ++mt)
#pragma unroll
        for (int rh = 0; rh < 2; ++rh)
#pragma unroll
            for (int jj = 0; jj < 4; ++jj) {
                int ch = 32 * w + 16 * mt + 8 * rh + r;
                int ps = (jj * 8 + 2 * q) ^ ((ch & 3) << 3);
                float4 u0 = *(const float4*)((float2*)buf + (0 * 128 + ch) * 32 + ps);
                float4 u1 = *(const float4*)((float2*)buf + (1 * 128 + ch) * 32 + ps);
                float4 u2 = *(const float4*)((float2*)buf + (2 * 128 + ch) * 32 + ps);
                float res[3][2];
#pragma unroll
                for (int e = 0; e < 2; ++e) {
                    int cr = rh * 2 + e;
                    float v0 = e ? (u0.z + u0.w) : (u0.x + u0.y);
                    float v1 = e ? (u1.z + u1.w) : (u1.x + u1.y);
                    float v2 = e ? (u2.z + u2.w) : (u2.x + u2.y);
                    vact(v0, v1, v2,
                         c2[mt][jj][cr], c2[mt][4 + jj][cr], c2[mt][8 + jj][cr],
                         res[0][e], res[1][e], res[2][e]);
                }
#pragma unroll
                for (int d = 0; d < 3; ++d)
                    *(float2*)(gdst + (d * 128 + ch) * 32 + jj * 8 + 2 * q) =
                        make_float2(res[d][0], res[d][1]);
            }
}

// ---------------- global mean over N of bufB -> g_g ------------------------
__global__ void mean_kernel() {
    int fl = blockIdx.x;                 // b*384 + row
    int b = fl / (3 * H), row = fl - b * (3 * H);
    const float* base = g_bufB + (size_t)b * 64 * BLKF + row * 32;
    float s = 0.0f;
    for (int i = threadIdx.x; i < 512; i += 128) {
        int blk = i >> 3, p4 = (i & 7) << 2;
        float4 v = *(const float4*)(base + blk * BLKF + p4);
        s += (v.x + v.y) + (v.z + v.w);
    }
    __shared__ float rs[4];
    for (int o = 16; o > 0; o >>= 1) s += __shfl_xor_sync(0xffffffffu, s, o);
    if ((threadIdx.x & 31) == 0) rs[threadIdx.x >> 5] = s;
    __syncthreads();
    if (threadIdx.x == 0)
        g_g[fl] = (rs[0] + rs[1] + rs[2] + rs[3]) * (1.0f / NPT);
}

// ---------------- gpart = Gs[:, H:2H] @ g per batch ------------------------
__global__ void gpart_kernel(const float* __restrict__ Gi) {
    int b = blockIdx.x;
    int t = threadIdx.x;                 // 384 threads: t = d*128 + h
    __shared__ float gs[3 * H];
    gs[t] = g_g[b * 3 * H + t];
    __syncthreads();
    int d = t >> 7, h = t & 127;
    const float4* w4p = (const float4*)(Gi + h * (2 * H) + H);
    const float4* g4p = (const float4*)&gs[d * H];
    float s = 0.0f;
#pragma unroll
    for (int c = 0; c < H / 4; ++c) {
        float4 w = w4p[c], v = g4p[c];
        s += w.x * v.x + w.y * v.y + w.z * v.z + w.w * v.w;
    }
    g_gp[b * 3 * H + t] = s;
}

// -------- G-layer via 3xTF32 tensor cores + W_out accumulation -------------
__global__ __launch_bounds__(128)
void glayer_tc(const float* __restrict__ Gl, const float* __restrict__ Gd,
               const float* __restrict__ Wout, float* __restrict__ obig,
               int layer) {
    extern __shared__ float buf[];
    __shared__ float red[4][32];
    int tid = threadIdx.x;
    int w = tid >> 5, lane = tid & 31, q = lane & 3, r = lane >> 2;
    int blk = blockIdx.x;
    int b = blk >> 6;
    int n0 = (blk & 63) * 32;

    const float4* gsrc = (const float4*)(g_bufB + blk * BLKF);
#pragma unroll 4
    for (int i = tid; i < 3072; i += 128) {
        float4 v = gsrc[i];
        int row = i >> 3, pw = (i & 7) << 2;
        float2* ds = (float2*)buf + row * 32 + (pw ^ ((row & 3) << 3));
        ds[0] = split32(v.x); ds[1] = split32(v.y);
        ds[2] = split32(v.z); ds[3] = split32(v.w);
    }
    __syncthreads();

    // init accumulators with the global-feature part (exact fp32)
    float c1[2][12][4];
    float gpv[2][2][3];
#pragma unroll
    for (int mt = 0; mt < 2; ++mt)
#pragma unroll
        for (int rh = 0; rh < 2; ++rh)
#pragma unroll
            for (int d = 0; d < 3; ++d)
                gpv[mt][rh][d] =
                    g_gp[b * 3 * H + d * H + 32 * w + 16 * mt + 8 * rh + r];
#pragma unroll
    for (int mt = 0; mt < 2; ++mt)
#pragma unroll
        for (int jn = 0; jn < 12; ++jn)
#pragma unroll
            for (int cr = 0; cr < 4; ++cr)
                c1[mt][jn][cr] = gpv[mt][cr >> 1][jn >> 2];
    gemm3_tc(Gl, 256, buf, c1, w, q, r);

    // channel-equivariant norm
    float n2[2][4][4];
#pragma unroll
    for (int mt = 0; mt < 2; ++mt)
#pragma unroll
        for (int jj = 0; jj < 4; ++jj)
#pragma unroll
            for (int cr = 0; cr < 4; ++cr)
                n2[mt][jj][cr] = c1[mt][jj][cr] * c1[mt][jj][cr]
                               + c1[mt][4 + jj][cr] * c1[mt][4 + jj][cr]
                               + c1[mt][8 + jj][cr] * c1[mt][8 + jj][cr];
    float lcn[4][2];
#pragma unroll
    for (int jj = 0; jj < 4; ++jj)
#pragma unroll
        for (int e = 0; e < 2; ++e)
            lcn[jj][e] = n2[0][jj][e] + n2[0][jj][e + 2]
                       + n2[1][jj][e] + n2[1][jj][e + 2];
#pragma unroll
    for (int o = 4; o < 32; o <<= 1)
#pragma unroll
        for (int jj = 0; jj < 4; ++jj)
#pragma unroll
            for (int e = 0; e < 2; ++e)
                lcn[jj][e] += __shfl_xor_sync(0xffffffffu, lcn[jj][e], o);
    if (r == 0)
#pragma unroll
        for (int jj = 0; jj < 4; ++jj)
#pragma unroll
            for (int e = 0; e < 2; ++e)
                red[w][jj * 8 + 2 * q + e] = lcn[jj][e];
    __syncthreads();

    float cns[4][2];
#pragma unroll
    for (int jj = 0; jj < 4; ++jj)
#pragma unroll
        for (int e = 0; e < 2; ++e) {
            int col = jj * 8 + 2 * q + e;
            cns[jj][e] = sqrtf(red[0][col] + red[1][col] + red[2][col] + red[3][col]);
        }

#pragma unroll
    for (int mt = 0; mt < 2; ++mt)
#pragma unroll
        for (int rh = 0; rh < 2; ++rh)
#pragma unroll
            for (int jj = 0; jj < 4; ++jj) {
                int ch = 32 * w + 16 * mt + 8 * rh + r;
                int ps = (jj * 8 + 2 * q) ^ ((ch & 3) << 3);
                float nA = sqrtf(n2[mt][jj][rh * 2]);
                float nB = sqrtf(n2[mt][jj][rh * 2 + 1]);
                float f0 = (nA / fmaxf(nA, EPS)) / fmaxf(cns[jj][0], EPS);
                float f1 = (nB / fmaxf(nB, EPS)) / fmaxf(cns[jj][1], EPS);
#pragma unroll
                for (int d = 0; d < 3; ++d) {
                    float2 s0 = split32(c1[mt][4 * d + jj][rh * 2] * f0);
                    float2 s1 = split32(c1[mt][4 * d + jj][rh * 2 + 1] * f1);
                    *(float4*)((float2*)buf + (d * 128 + ch) * 32 + ps) =
                        make_float4(s0.x, s0.y, s1.x, s1.y);
                }
            }
    __syncthreads();

    float c2[2][12][4];
#pragma unroll
    for (int mt = 0; mt < 2; ++mt)
#pragma unroll
        for (int jn = 0; jn < 12; ++jn)
#pragma unroll
            for (int cr = 0; cr < 4; ++cr) c2[mt][jn][cr] = 0.0f;
    gemm3_tc(Gd, 128, buf, c2, w, q, r);
    __syncthreads();   // all GEMM2 reads of buf done before h2 overwrites

    // vact -> h2: store to g_bufA (next layer) and buf (for W_out GEMM)
    float* gdst = g_bufA + blk * BLKF;
#pragma unroll
    for (int mt = 0; mt < 2; ++mt)
#pragma unroll
        for (int rh = 0; rh < 2; ++rh)
#pragma unroll
            for (int jj = 0; jj < 4; ++jj) {
                int ch = 32 * w + 16 * mt + 8 * rh + r;
                int ps = (jj * 8 + 2 * q) ^ ((ch & 3) << 3);
                float4 u0 = *(const float4*)((float2*)buf + (0 * 128 + ch) * 32 + ps);
                float4 u1 = *(const float4*)((float2*)buf + (1 * 128 + ch) * 32 + ps);
                float4 u2 = *(const float4*)((float2*)buf + (2 * 128 + ch) * 32 + ps);
                float res[3][2];
#pragma unroll
                for (int e = 0; e < 2; ++e) {
                    int cr = rh * 2 + e;
                    float v0 = e ? (u0.z + u0.w) : (u0.x + u0.y);
                    float v1 = e ? (u1.z + u1.w) : (u1.x + u1.y);
                    float v2 = e ? (u2.z + u2.w) : (u2.x + u2.y);
                    vact(v0, v1, v2,
                         c2[mt][jj][cr], c2[mt][4 + jj][cr], c2[mt][8 + jj][cr],
                         res[0][e], res[1][e], res[2][e]);
                }
#pragma unroll
                for (int d = 0; d < 3; ++d) {
                    *(float2*)(gdst + (d * 128 + ch) * 32 + jj * 8 + 2 * q) =
                        make_float2(res[d][0], res[d][1]);
                    float2 s0 = split32(res[d][0]);
                    float2 s1 = split32(res[d][1]);
                    *(float4*)((float2*)buf + (d * 128 + ch) * 32 + ps) =
                        make_float4(s0.x, s0.y, s1.x, s1.y);
                }
            }
    __syncthreads();

    float c3[2][12][4];
#pragma unroll
    for (int mt = 0; mt < 2; ++mt)
#pragma unroll
        for (int jn = 0; jn < 12; ++jn)
#pragma unroll
            for (int cr = 0; cr < 4; ++cr) c3[mt][jn][cr] = 0.0f;
    gemm3_tc(Wout + layer * H, LL * H, buf, c3, w, q, r);

#pragma unroll
    for (int mt = 0; mt < 2; ++mt)
#pragma unroll
        for (int rh = 0; rh < 2; ++rh)
#pragma unroll
            for (int jj = 0; jj < 4; ++jj) {
                int ch = 32 * w + 16 * mt + 8 * rh + r;
#pragma unroll
                for (int d = 0; d < 3; ++d) {
                    float2* dp = (float2*)(obig +
                        ((size_t)(b * CDIM + ch) * 3 + d) * NPT + n0 + jj * 8 + 2 * q);
                    float v0 = c3[mt][4 * d + jj][rh * 2];
                    float v1 = c3[mt][4 * d + jj][rh * 2 + 1];
                    if (layer == 0) {
                        *dp = make_float2(v0, v1);
                    } else {
                        float2 e = *dp;
                        *dp = make_float2(e.x + v0, e.y + v1);
                    }
                }
            }
}

// ---------------- final mean over N of the big output ----------------------
__global__ void outmean_kernel(const float* __restrict__ obig,
                               float* __restrict__ om) {
    int r = blockIdx.x;                  // (b*CD + cd)*3 + d
    float s = 0.0f;
    for (int n = threadIdx.x; n < NPT; n += blockDim.x)
        s += obig[(size_t)r * NPT + n];
    __shared__ float rs[8];
    for (int o = 16; o > 0; o >>= 1) s += __shfl_xor_sync(0xffffffffu, s, o);
    if ((threadIdx.x & 31) == 0) rs[threadIdx.x >> 5] = s;
    __syncthreads();
    if (threadIdx.x == 0) {
        float t = 0.0f;
#pragma unroll
        for (int w = 0; w < 8; ++w) t += rs[w];
        om[r] = t * (1.0f / NPT);
    }
}

// ---------------------------------------------------------------------------
extern "C" void kernel_launch(void* const* d_in, const int* in_sizes, int n_in,
                              void* d_out, int out_size) {
    const float* x    = (const float*)d_in[0];
    const float* Win  = (const float*)d_in[1];
    const float* Wdin = (const float*)d_in[2];
    const float* Ws   = (const float*)d_in[3];
    const float* Wds  = (const float*)d_in[4];
    const float* Gs   = (const float*)d_in[5];
    const float* Gds  = (const float*)d_in[6];
    const float* Wout = (const float*)d_in[7];
    (void)in_sizes; (void)n_in; (void)out_size;

    float* out  = (float*)d_out;
    float* om   = out;                    // (B, CD, 3) mean
    float* obig = out + BB * CDIM * 3;    // (B, CD, 3, N)

    const int smem = 3 * 128 * 32 * 2 * 4;  // 96 KB dynamic (hi/lo slots)

    // Opt in to >48KB smem. Host-side, idempotent, graph-capture safe.
    cudaFuncSetAttribute(lna_tc, cudaFuncAttributeMaxDynamicSharedMemorySize, smem);
    cudaFuncSetAttribute(glayer_tc, cudaFuncAttributeMaxDynamicSharedMemorySize, smem);

    knn_kernel<<<dim3(NPT / 128, BB), 128>>>(x);
    input_kernel<<<BB * NPT, 256>>>(x, Win, Wdin);

    for (int i = 0; i < LL; ++i) {
        lna_tc<<<NBLK, 128, smem>>>(Ws + i * H * H, Wds + i * H * H);
        mean_kernel<<<BB * 3 * H, 128>>>();
        gpart_kernel<<<BB, 3 * H>>>(Gs + i * H * 2 * H);
        glayer_tc<<<NBLK, 128, smem>>>(Gs + i * H * 2 * H,
                                       Gds + i * H * H,
                                       Wout, obig, i);
    }
    outmean_kernel<<<BB * CDIM * 3, 256>>>(obig, om);
}

// round 12
// speedup vs baseline: 2.0569x; 1.3950x over previous
#include <cuda_runtime.h>
#include <cuda_bf16.h>

#define BB   8
#define NPT  2048
#define KNN  16
#define H    128
#define LL   4
#define CDIM 128
#define EPS  1e-12f
#define TBLK 32                       // points per tc block
#define NBLK (BB * NPT / TBLK)        // 512 tc blocks
#define BLKF (3 * H * TBLK)           // 12288 floats per block tile [d][c][p32]

// ---------------- scratch (static device globals; no runtime alloc) --------
__device__ __align__(16) float g_bufA[NBLK * BLKF];
__device__ __align__(16) float g_bufB[NBLK * BLKF];
__device__ int   g_idx[BB * NPT * KNN];
__device__ float g_g [BB * 3 * H];
__device__ float g_gp[BB * 3 * H];
__device__ float g_M [6];            // Win^T Win (3x3 symmetric): aa,bb,cc,ab,ac,bc

// ---------------- helpers --------------------------------------------------
__device__ __forceinline__ unsigned tf32r(float f) {
    unsigned u; asm("cvt.rna.tf32.f32 %0, %1;" : "=r"(u) : "f"(f)); return u;
}
__device__ __forceinline__ float tf32f(float f) { return __uint_as_float(tf32r(f)); }
// hi/lo split for 3xTF32: v ~= hi + lo, each tf32-representable
__device__ __forceinline__ float2 split32(float v) {
    float hi = tf32f(v);
    float lo = tf32f(v - hi);
    return make_float2(hi, lo);
}

__device__ __forceinline__ void mma8(float* c, const unsigned* a,
                                     unsigned b0, unsigned b1) {
    asm volatile(
        "mma.sync.aligned.m16n8k8.row.col.f32.tf32.tf32.f32 "
        "{%0,%1,%2,%3}, {%4,%5,%6,%7}, {%8,%9}, {%0,%1,%2,%3};"
        : "+f"(c[0]), "+f"(c[1]), "+f"(c[2]), "+f"(c[3])
        : "r"(a[0]), "r"(a[1]), "r"(a[2]), "r"(a[3]), "r"(b0), "r"(b1));
}

__device__ __forceinline__ void vact(float v0, float v1, float v2,
                                     float k0, float k1, float k2,
                                     float& r0, float& r1, float& r2) {
    float kn  = sqrtf(k0 * k0 + k1 * k1 + k2 * k2);
    float inv = 1.0f / fmaxf(kn, EPS);
    float a = k0 * inv, b = k1 * inv, c = k2 * inv;
    float dot = v0 * a + v1 * b + v2 * c;
    float s = fminf(dot, 0.0f);
    r0 = v0 - s * a; r1 = v1 - s * b; r2 = v2 - s * c;
}

// 3xTF32 GEMM: C[128h x 96col] = A[128x128] * act[128c x 96col], col = d*32+p.
// buf slots are float2 {hi,lo}, slot index = row*32 + (p ^ ((row&3)<<3)).
// Warp w owns rows 32w..32w+31; lane -> q = lane&3, r = lane>>2.
__device__ __forceinline__ void gemm3_tc(const float* __restrict__ A, int ws,
                                         const float* __restrict__ buf,
                                         float c[2][12][4], int w, int q, int r) {
    const float* a0p = A + (32 * w + r) * ws;
    const float* a1p = a0p + 8 * ws;
    const float* a2p = a0p + 16 * ws;
    const float* a3p = a0p + 24 * ws;
    int swz = q << 3;
#pragma unroll 2
    for (int k8 = 0; k8 < 16; ++k8) {
        int kb = k8 * 8;
        float af[2][4];
        af[0][0] = a0p[kb + q];     af[0][1] = a1p[kb + q];
        af[0][2] = a0p[kb + q + 4]; af[0][3] = a1p[kb + q + 4];
        af[1][0] = a2p[kb + q];     af[1][1] = a3p[kb + q];
        af[1][2] = a2p[kb + q + 4]; af[1][3] = a3p[kb + q + 4];
        unsigned ah[2][4], al[2][4];
#pragma unroll
        for (int mt = 0; mt < 2; ++mt)
#pragma unroll
            for (int t = 0; t < 4; ++t) {
                ah[mt][t] = tf32r(af[mt][t]);
                al[mt][t] = tf32r(af[mt][t] - __uint_as_float(ah[mt][t]));
            }
#pragma unroll
        for (int jn = 0; jn < 12; ++jn) {
            int d = jn >> 2;
            int boff = (((jn & 3) * 8) ^ swz) + r;
            float2 b0 = *(const float2*)(buf + ((d * 128 + kb + q) * 32 + boff) * 2);
            float2 b1 = *(const float2*)(buf + ((d * 128 + kb + q + 4) * 32 + boff) * 2);
            unsigned bh0 = __float_as_uint(b0.x), bl0 = __float_as_uint(b0.y);
            unsigned bh1 = __float_as_uint(b1.x), bl1 = __float_as_uint(b1.y);
            mma8(c[0][jn], ah[0], bh0, bh1);
            mma8(c[1][jn], ah[1], bh0, bh1);
            mma8(c[0][jn], ah[0], bl0, bl1);
            mma8(c[1][jn], ah[1], bl0, bl1);
            mma8(c[0][jn], al[0], bh0, bh1);
            mma8(c[1][jn], al[1], bh0, bh1);
        }
    }
}

// ---------------- kNN: register-resident branch-free top-16 ----------------
__global__ __launch_bounds__(128)
void knn_kernel(const float* __restrict__ x) {
    int b = blockIdx.y;
    int i = blockIdx.x * blockDim.x + threadIdx.x;
    __shared__ float px[NPT], py[NPT], pz[NPT], sq[NPT];
    const float* xb = x + b * 3 * NPT;
    for (int n = threadIdx.x; n < NPT; n += blockDim.x) {
        float a = xb[n], c = xb[NPT + n], e = xb[2 * NPT + n];
        px[n] = a; py[n] = c; pz[n] = e;
        sq[n] = a * a + c * c + e * e;
    }
    __syncthreads();
    float qx = px[i], qy = py[i], qz = pz[i], qs = sq[i];
    float bd[KNN]; int bi[KNN];
#pragma unroll
    for (int t = 0; t < KNN; ++t) { bd[t] = 3.4e38f; bi[t] = 0; }
#pragma unroll 4
    for (int j = 0; j < NPT; ++j) {
        float dot = qx * px[j] + qy * py[j] + qz * pz[j];
        float d2  = fmaf(-2.0f, dot, qs + sq[j]);
        if (d2 < bd[KNN - 1]) {
            float cd = d2; int ci = j;
#pragma unroll
            for (int t = 0; t < KNN; ++t) {
                bool lt = cd < bd[t];
                float nd = lt ? cd    : bd[t];
                int   ni = lt ? ci    : bi[t];
                float od = lt ? bd[t] : cd;
                int   oi = lt ? bi[t] : ci;
                bd[t] = nd; bi[t] = ni;
                cd = od; ci = oi;
            }
        }
    }
    int base = (b * NPT + i) * KNN;
#pragma unroll
    for (int t = 0; t < KNN; ++t) g_idx[base + t] = bi[t];
}

// ---------------- M = Win^T Win (3x3 symmetric, once) -----------------------
__global__ void mwin_kernel(const float* __restrict__ Win) {
    int lane = threadIdx.x;              // 32 threads
    float m[6] = {0, 0, 0, 0, 0, 0};
    for (int hh = lane; hh < H; hh += 32) {
        float a = Win[hh * 3], bb = Win[hh * 3 + 1], cc = Win[hh * 3 + 2];
        m[0] += a * a;  m[1] += bb * bb; m[2] += cc * cc;
        m[3] += a * bb; m[4] += a * cc;  m[5] += bb * cc;
    }
#pragma unroll
    for (int o = 16; o > 0; o >>= 1)
#pragma unroll
        for (int i = 0; i < 6; ++i)
            m[i] += __shfl_xor_sync(0xffffffffu, m[i], o);
    if (lane == 0)
#pragma unroll
        for (int i = 0; i < 6; ++i) g_M[i] = m[i];
}

// ---------------- input stage via 3xTF32 tensor cores -----------------------
// 2 points per block (8192 blocks). Cols p = pt*16 + k (32 slots).
__global__ __launch_bounds__(128)
void input_tc(const float* __restrict__ x,
              const float* __restrict__ Win,
              const float* __restrict__ Wdin) {
    extern __shared__ float buf[];       // float2 hi/lo slots, 96 KB
    __shared__ float ysh[3][3][32];      // [ch][d][p]
    __shared__ float invcn[32];
    int tid = threadIdx.x;
    int w = tid >> 5, lane = tid & 31, q = lane & 3, r = lane >> 2;
    int gp0 = blockIdx.x * 2;            // 2 consecutive global points
    int b = gp0 >> 11;

    // phase 1: warp 0 builds y features + channel-norm denominator (3x3 form)
    if (tid < 32) {
        int p = tid, pt = p >> 4, k = p & 15;
        int nl = (gp0 & (NPT - 1)) + pt;
        const float* xb = x + b * 3 * NPT;
        float cx = xb[nl], cy = xb[NPT + nl], cz = xb[2 * NPT + nl];
        int j = g_idx[(b * NPT + nl) * KNN + k];
        float nx = xb[j], ny = xb[NPT + j], nz = xb[2 * NPT + j];
        float nn  = sqrtf(cx * cx + cy * cy + cz * cz);
        float inv = 1.0f / fmaxf(nn, EPS);
        float dx = cx * inv, dy = cy * inv, dz = cz * inv;
        float y0[3] = {dy * nz - dz * ny, dz * nx - dx * nz, dx * ny - dy * nx};
        float y1[3] = {nx - cx, ny - cy, nz - cz};
        float y2[3] = {cx, cy, cz};
#pragma unroll
        for (int d = 0; d < 3; ++d) {
            ysh[0][d][p] = y0[d]; ysh[1][d][p] = y1[d]; ysh[2][d][p] = y2[d];
        }
        float m0 = g_M[0], m1 = g_M[1], m2 = g_M[2];
        float m3 = g_M[3], m4 = g_M[4], m5 = g_M[5];
        float s = 0.0f;
#pragma unroll
        for (int d = 0; d < 3; ++d) {
            float a = y0[d], bb = y1[d], cc = y2[d];
            s += m0 * a * a + m1 * bb * bb + m2 * cc * cc
               + 2.0f * (m3 * a * bb + m4 * a * cc + m5 * bb * cc);
        }
        invcn[p] = 1.0f / fmaxf(sqrtf(s), EPS);
    }
    __syncthreads();

    // phase 2: thread = h, build normalized v (hi/lo) into buf.
    // p loop rotated by lane so STS across the warp are conflict-free.
    {
        int h = tid;
        float w0 = Win[h * 3 + 0], w1 = Win[h * 3 + 1], w2 = Win[h * 3 + 2];
        int hs = (h & 3) << 3;
#pragma unroll 4
        for (int pp = 0; pp < 32; ++pp) {
            int p = (pp + lane) & 31;
            float icn = invcn[p];
            float u[3];
#pragma unroll
            for (int d = 0; d < 3; ++d)
                u[d] = w0 * ysh[0][d][p] + w1 * ysh[1][d][p] + w2 * ysh[2][d][p];
            float nsq = u[0] * u[0] + u[1] * u[1] + u[2] * u[2];
            float f = (nsq >= 1e-24f) ? icn : (sqrtf(nsq) * 1e12f * icn);
            int pswz = p ^ hs;
#pragma unroll
            for (int d = 0; d < 3; ++d)
                ((float2*)buf)[(d * 128 + h) * 32 + pswz] = split32(u[d] * f);
        }
    }
    __syncthreads();

    // phase 3: kv = Wd_in @ v  (3xTF32 tensor cores)
    float c[2][12][4];
#pragma unroll
    for (int mt = 0; mt < 2; ++mt)
#pragma unroll
        for (int jn = 0; jn < 12; ++jn)
#pragma unroll
            for (int cr = 0; cr < 4; ++cr) c[mt][jn][cr] = 0.0f;
    gemm3_tc(Wdin, 128, buf, c, w, q, r);

    // phase 4: vact + mean over K (shfl over q lanes) + store to g_bufA
    const float inv16 = 1.0f / 16.0f;
#pragma unroll
    for (int mt = 0; mt < 2; ++mt)
#pragma unroll
        for (int rh = 0; rh < 2; ++rh) {
            int ch = 32 * w + 16 * mt + 8 * rh + r;
            float acc[2][3];
#pragma unroll
            for (int pt = 0; pt < 2; ++pt)
#pragma unroll
                for (int d = 0; d < 3; ++d) acc[pt][d] = 0.0f;
#pragma unroll
            for (int jj = 0; jj < 4; ++jj) {
                int ps = (jj * 8 + 2 * q) ^ ((ch & 3) << 3);
                float4 u0 = *(const float4*)((float2*)buf + (0 * 128 + ch) * 32 + ps);
                float4 u1 = *(const float4*)((float2*)buf + (1 * 128 + ch) * 32 + ps);
                float4 u2 = *(const float4*)((float2*)buf + (2 * 128 + ch) * 32 + ps);
                int pt = jj >> 1;
#pragma unroll
                for (int e = 0; e < 2; ++e) {
                    int cr = rh * 2 + e;
                    float v0 = e ? (u0.z + u0.w) : (u0.x + u0.y);
                    float v1 = e ? (u1.z + u1.w) : (u1.x + u1.y);
                    float v2 = e ? (u2.z + u2.w) : (u2.x + u2.y);
                    float r0, r1, r2;
                    vact(v0, v1, v2,
                         c[mt][jj][cr], c[mt][4 + jj][cr], c[mt][8 + jj][cr],
                         r0, r1, r2);
                    acc[pt][0] += r0; acc[pt][1] += r1; acc[pt][2] += r2;
                }
            }
#pragma unroll
            for (int pt = 0; pt < 2; ++pt)
#pragma unroll
                for (int d = 0; d < 3; ++d) {
                    acc[pt][d] += __shfl_xor_sync(0xffffffffu, acc[pt][d], 1);
                    acc[pt][d] += __shfl_xor_sync(0xffffffffu, acc[pt][d], 2);
                }
            if (q == 0) {
                int tb = gp0 >> 5, tp = gp0 & 31;   // gp0 even -> both pts same tile
#pragma unroll
                for (int d = 0; d < 3; ++d)
                    *(float2*)(g_bufA + tb * BLKF + (d * 128 + ch) * 32 + tp) =
                        make_float2(acc[0][d] * inv16, acc[1][d] * inv16);
            }
        }
}

// ---------------- lna via 3xTF32 tensor cores: bufA -> bufB -----------------
__global__ __launch_bounds__(128)
void lna_tc(const float* __restrict__ W, const float* __restrict__ Wd) {
    extern __shared__ float buf[];       // float2 hi/lo slots, 96 KB
    __shared__ float red[4][32];
    int tid = threadIdx.x;
    int w = tid >> 5, lane = tid & 31, q = lane & 3, r = lane >> 2;
    int blk = blockIdx.x;

    const float4* gsrc = (const float4*)(g_bufA + blk * BLKF);
#pragma unroll 4
    for (int i = tid; i < 3072; i += 128) {
        float4 v = gsrc[i];
        int row = i >> 3, pw = (i & 7) << 2;
        float2* ds = (float2*)buf + row * 32 + (pw ^ ((row & 3) << 3));
        ds[0] = split32(v.x); ds[1] = split32(v.y);
        ds[2] = split32(v.z); ds[3] = split32(v.w);
    }
    __syncthreads();

    float c1[2][12][4];
#pragma unroll
    for (int mt = 0; mt < 2; ++mt)
#pragma unroll
        for (int jn = 0; jn < 12; ++jn)
#pragma unroll
            for (int cr = 0; cr < 4; ++cr) c1[mt][jn][cr] = 0.0f;
    gemm3_tc(W, 128, buf, c1, w, q, r);

    // channel-equivariant norm
    float n2[2][4][4];
#pragma unroll
    for (int mt = 0; mt < 2; ++mt)
#pragma unroll
        for (int jj = 0; jj < 4; ++jj)
#pragma unroll
            for (int cr = 0; cr < 4; ++cr)
                n2[mt][jj][cr] = c1[mt][jj][cr] * c1[mt][jj][cr]
                               + c1[mt][4 + jj][cr] * c1[mt][4 + jj][cr]
                               + c1[mt][8 + jj][cr] * c1[mt][8 + jj][cr];
    float lcn[4][2];
#pragma unroll
    for (int jj = 0; jj < 4; ++jj)
#pragma unroll
        for (int e = 0; e < 2; ++e)
            lcn[jj][e] = n2[0][jj][e] + n2[0][jj][e + 2]
                       + n2[1][jj][e] + n2[1][jj][e + 2];
#pragma unroll
    for (int o = 4; o < 32; o <<= 1)
#pragma unroll
        for (int jj = 0; jj < 4; ++jj)
#pragma unroll
            for (int e = 0; e < 2; ++e)
                lcn[jj][e] += __shfl_xor_sync(0xffffffffu, lcn[jj][e], o);
    if (r == 0)
#pragma unroll
        for (int jj = 0; jj < 4; ++jj)
#pragma unroll
            for (int e = 0; e < 2; ++e)
                red[w][jj * 8 + 2 * q + e] = lcn[jj][e];
    __syncthreads();

    float cns[4][2];
#pragma unroll
    for (int jj = 0; jj < 4; ++jj)
#pragma unroll
        for (int e = 0; e < 2; ++e) {
            int col = jj * 8 + 2 * q + e;
            cns[jj][e] = sqrtf(red[0][col] + red[1][col] + red[2][col] + red[3][col]);
        }

    // scale + store v' (hi/lo) back into buf
#pragma unroll
    for (int mt = 0; mt < 2; ++mt)
#pragma unroll
        for (int rh = 0; rh < 2; ++rh)
#pragma unroll
            for (int jj = 0; jj < 4; ++jj) {
                int ch = 32 * w + 16 * mt + 8 * rh + r;
                int ps = (jj * 8 + 2 * q) ^ ((ch & 3) << 3);
                float nA = sqrtf(n2[mt][jj][rh * 2]);
                float nB = sqrtf(n2[mt][jj][rh * 2 + 1]);
                float f0 = (nA / fmaxf(nA, EPS)) / fmaxf(cns[jj][0], EPS);
                float f1 = (nB / fmaxf(nB, EPS)) / fmaxf(cns[jj][1], EPS);
#pragma unroll
                for (int d = 0; d < 3; ++d) {
                    float2 s0 = split32(c1[mt][4 * d + jj][rh * 2] * f0);
                    float2 s1 = split32(c1[mt][4 * d + jj][rh * 2 + 1] * f1);
                    *(float4*)((float2*)buf + (d * 128 + ch) * 32 + ps) =
                        make_float4(s0.x, s0.y, s1.x, s1.y);
                }
            }
    __syncthreads();

    float c2[2][12][4];
#pragma unroll
    for (int mt = 0; mt < 2; ++mt)
#pragma unroll
        for (int jn = 0; jn < 12; ++jn)
#pragma unroll
            for (int cr = 0; cr < 4; ++cr) c2[mt][jn][cr] = 0.0f;
    gemm3_tc(Wd, 128, buf, c2, w, q, r);

    // vact + store to g_bufB (plain fp32 layout)
    float* gdst = g_bufB + blk * BLKF;
#pragma unroll
    for (int mt = 0; mt < 2; ++mt)
#pragma unroll
        for (int rh = 0; rh < 2; ++rh)
#pragma unroll
            for (int jj = 0; jj < 4; ++jj) {
                int ch = 32 * w + 16 * mt + 8 * rh + r;
                int ps = (jj * 8 + 2 * q) ^ ((ch & 3) << 3);
                float4 u0 = *(const float4*)((float2*)buf + (0 * 128 + ch) * 32 + ps);
                float4 u1 = *(const float4*)((float2*)buf + (1 * 128 + ch) * 32 + ps);
                float4 u2 = *(const float4*)((float2*)buf + (2 * 128 + ch) * 32 + ps);
                float res[3][2];
#pragma unroll
                for (int e = 0; e < 2; ++e) {
                    int cr = rh * 2 + e;
                    float v0 = e ? (u0.z + u0.w) : (u0.x + u0.y);
                    float v1 = e ? (u1.z + u1.w) : (u1.x + u1.y);
                    float v2 = e ? (u2.z + u2.w) : (u2.x + u2.y);
                    vact(v0, v1, v2,
                         c2[mt][jj][cr], c2[mt][4 + jj][cr], c2[mt][8 + jj][cr],
                         res[0][e], res[1][e], res[2][e]);
                }
#pragma unroll
                for (int d = 0; d < 3; ++d)
                    *(float2*)(gdst + (d * 128 + ch) * 32 + jj * 8 + 2 * q) =
                        make_float2(res[d][0], res[d][1]);
            }
}

// ---------------- global mean over N of bufB -> g_g ------------------------
__global__ void mean_kernel() {
    int fl = blockIdx.x;                 // b*384 + row
    int b = fl / (3 * H), row = fl - b * (3 * H);
    const float* base = g_bufB + (size_t)b * 64 * BLKF + row * 32;
    float s = 0.0f;
    for (int i = threadIdx.x; i < 512; i += 128) {
        int blk = i >> 3, p4 = (i & 7) << 2;
        float4 v = *(const float4*)(base + blk * BLKF + p4);
        s += (v.x + v.y) + (v.z + v.w);
    }
    __shared__ float rs[4];
    for (int o = 16; o > 0; o >>= 1) s += __shfl_xor_sync(0xffffffffu, s, o);
    if ((threadIdx.x & 31) == 0) rs[threadIdx.x >> 5] = s;
    __syncthreads();
    if (threadIdx.x == 0)
        g_g[fl] = (rs[0] + rs[1] + rs[2] + rs[3]) * (1.0f / NPT);
}

// ---------------- gpart = Gs[:, H:2H] @ g per batch ------------------------
__global__ void gpart_kernel(const float* __restrict__ Gi) {
    int b = blockIdx.x;
    int t = threadIdx.x;                 // 384 threads: t = d*128 + h
    __shared__ float gs[3 * H];
    gs[t] = g_g[b * 3 * H + t];
    __syncthreads();
    int d = t >> 7, h = t & 127;
    const float4* w4p = (const float4*)(Gi + h * (2 * H) + H);
    const float4* g4p = (const float4*)&gs[d * H];
    float s = 0.0f;
#pragma unroll
    for (int c = 0; c < H / 4; ++c) {
        float4 w = w4p[c], v = g4p[c];
        s += w.x * v.x + w.y * v.y + w.z * v.z + w.w * v.w;
    }
    g_gp[b * 3 * H + t] = s;
}

// -------- G-layer via 3xTF32 tensor cores + W_out accumulation -------------
__global__ __launch_bounds__(128)
void glayer_tc(const float* __restrict__ Gl, const float* __restrict__ Gd,
               const float* __restrict__ Wout, float* __restrict__ obig,
               int layer) {
    extern __shared__ float buf[];
    __shared__ float red[4][32];
    int tid = threadIdx.x;
    int w = tid >> 5, lane = tid & 31, q = lane & 3, r = lane >> 2;
    int blk = blockIdx.x;
    int b = blk >> 6;
    int n0 = (blk & 63) * 32;

    const float4* gsrc = (const float4*)(g_bufB + blk * BLKF);
#pragma unroll 4
    for (int i = tid; i < 3072; i += 128) {
        float4 v = gsrc[i];
        int row = i >> 3, pw = (i & 7) << 2;
        float2* ds = (float2*)buf + row * 32 + (pw ^ ((row & 3) << 3));
        ds[0] = split32(v.x); ds[1] = split32(v.y);
        ds[2] = split32(v.z); ds[3] = split32(v.w);
    }
    __syncthreads();

    // init accumulators with the global-feature part (exact fp32)
    float c1[2][12][4];
    float gpv[2][2][3];
#pragma unroll
    for (int mt = 0; mt < 2; ++mt)
#pragma unroll
        for (int rh = 0; rh < 2; ++rh)
#pragma unroll
            for (int d = 0; d < 3; ++d)
                gpv[mt][rh][d] =
                    g_gp[b * 3 * H + d * H + 32 * w + 16 * mt + 8 * rh + r];
#pragma unroll
    for (int mt = 0; mt < 2; ++mt)
#pragma unroll
        for (int jn = 0; jn < 12; ++jn)
#pragma unroll
            for (int cr = 0; cr < 4; ++cr)
                c1[mt][jn][cr] = gpv[mt][cr >> 1][jn >> 2];
    gemm3_tc(Gl, 256, buf, c1, w, q, r);

    // channel-equivariant norm
    float n2[2][4][4];
#pragma unroll
    for (int mt = 0; mt < 2; ++mt)
#pragma unroll
        for (int jj = 0; jj < 4; ++jj)
#pragma unroll
            for (int cr = 0; cr < 4; ++cr)
                n2[mt][jj][cr] = c1[mt][jj][cr] * c1[mt][jj][cr]
                               + c1[mt][4 + jj][cr] * c1[mt][4 + jj][cr]
                               + c1[mt][8 + jj][cr] * c1[mt][8 + jj][cr];
    float lcn[4][2];
#pragma unroll
    for (int jj = 0; jj < 4; ++jj)
#pragma unroll
        for (int e = 0; e < 2; ++e)
            lcn[jj][e] = n2[0][jj][e] + n2[0][jj][e + 2]
                       + n2[1][jj][e] + n2[1][jj][e + 2];
#pragma unroll
    for (int o = 4; o < 32; o <<= 1)
#pragma unroll
        for (int jj = 0; jj < 4; ++jj)
#pragma unroll
            for (int e = 0; e < 2; ++e)
                lcn[jj][e] += __shfl_xor_sync(0xffffffffu, lcn[jj][e], o);
    if (r == 0)
#pragma unroll
        for (int jj = 0; jj < 4; ++jj)
#pragma unroll
            for (int e = 0; e < 2; ++e)
                red[w][jj * 8 + 2 * q + e] = lcn[jj][e];
    __syncthreads();

    float cns[4][2];
#pragma unroll
    for (int jj = 0; jj < 4; ++jj)
#pragma unroll
        for (int e = 0; e < 2; ++e) {
            int col = jj * 8 + 2 * q + e;
            cns[jj][e] = sqrtf(red[0][col] + red[1][col] + red[2][col] + red[3][col]);
        }

#pragma unroll
    for (int mt = 0; mt < 2; ++mt)
#pragma unroll
        for (int rh = 0; rh < 2; ++rh)
#pragma unroll
            for (int jj = 0; jj < 4; ++jj) {
                int ch = 32 * w + 16 * mt + 8 * rh + r;
                int ps = (jj * 8 + 2 * q) ^ ((ch & 3) << 3);
                float nA = sqrtf(n2[mt][jj][rh * 2]);
                float nB = sqrtf(n2[mt][jj][rh * 2 + 1]);
                float f0 = (nA / fmaxf(nA, EPS)) / fmaxf(cns[jj][0], EPS);
                float f1 = (nB / fmaxf(nB, EPS)) / fmaxf(cns[jj][1], EPS);
#pragma unroll
                for (int d = 0; d < 3; ++d) {
                    float2 s0 = split32(c1[mt][4 * d + jj][rh * 2] * f0);
                    float2 s1 = split32(c1[mt][4 * d + jj][rh * 2 + 1] * f1);
                    *(float4*)((float2*)buf + (d * 128 + ch) * 32 + ps) =
                        make_float4(s0.x, s0.y, s1.x, s1.y);
                }
            }
    __syncthreads();

    float c2[2][12][4];
#pragma unroll
    for (int mt = 0; mt < 2; ++mt)
#pragma unroll
        for (int jn = 0; jn < 12; ++jn)
#pragma unroll
            for (int cr = 0; cr < 4; ++cr) c2[mt][jn][cr] = 0.0f;
    gemm3_tc(Gd, 128, buf, c2, w, q, r);
    __syncthreads();   // all GEMM2 reads of buf done before h2 overwrites

    // vact -> h2: store to g_bufA (next layer) and buf (for W_out GEMM)
    float* gdst = g_bufA + blk * BLKF;
#pragma unroll
    for (int mt = 0; mt < 2; ++mt)
#pragma unroll
        for (int rh = 0; rh < 2; ++rh)
#pragma unroll
            for (int jj = 0; jj < 4; ++jj) {
                int ch = 32 * w + 16 * mt + 8 * rh + r;
                int ps = (jj * 8 + 2 * q) ^ ((ch & 3) << 3);
                float4 u0 = *(const float4*)((float2*)buf + (0 * 128 + ch) * 32 + ps);
                float4 u1 = *(const float4*)((float2*)buf + (1 * 128 + ch) * 32 + ps);
                float4 u2 = *(const float4*)((float2*)buf + (2 * 128 + ch) * 32 + ps);
                float res[3][2];
#pragma unroll
                for (int e = 0; e < 2; ++e) {
                    int cr = rh * 2 + e;
                    float v0 = e ? (u0.z + u0.w) : (u0.x + u0.y);
                    float v1 = e ? (u1.z + u1.w) : (u1.x + u1.y);
                    float v2 = e ? (u2.z + u2.w) : (u2.x + u2.y);
                    vact(v0, v1, v2,
                         c2[mt][jj][cr], c2[mt][4 + jj][cr], c2[mt][8 + jj][cr],
                         res[0][e], res[1][e], res[2][e]);
                }
#pragma unroll
                for (int d = 0; d < 3; ++d) {
                    *(float2*)(gdst + (d * 128 + ch) * 32 + jj * 8 + 2 * q) =
                        make_float2(res[d][0], res[d][1]);
                    float2 s0 = split32(res[d][0]);
                    float2 s1 = split32(res[d][1]);
                    *(float4*)((float2*)buf + (d * 128 + ch) * 32 + ps) =
                        make_float4(s0.x, s0.y, s1.x, s1.y);
                }
            }
    __syncthreads();

    float c3[2][12][4];
#pragma unroll
    for (int mt = 0; mt < 2; ++mt)
#pragma unroll
        for (int jn = 0; jn < 12; ++jn)
#pragma unroll
            for (int cr = 0; cr < 4; ++cr) c3[mt][jn][cr] = 0.0f;
    gemm3_tc(Wout + layer * H, LL * H, buf, c3, w, q, r);

#pragma unroll
    for (int mt = 0; mt < 2; ++mt)
#pragma unroll
        for (int rh = 0; rh < 2; ++rh)
#pragma unroll
            for (int jj = 0; jj < 4; ++jj) {
                int ch = 32 * w + 16 * mt + 8 * rh + r;
#pragma unroll
                for (int d = 0; d < 3; ++d) {
                    float2* dp = (float2*)(obig +
                        ((size_t)(b * CDIM + ch) * 3 + d) * NPT + n0 + jj * 8 + 2 * q);
                    float v0 = c3[mt][4 * d + jj][rh * 2];
                    float v1 = c3[mt][4 * d + jj][rh * 2 + 1];
                    if (layer == 0) {
                        *dp = make_float2(v0, v1);
                    } else {
                        float2 e = *dp;
                        *dp = make_float2(e.x + v0, e.y + v1);
                    }
                }
            }
}

// ---------------- final mean over N of the big output ----------------------
__global__ void outmean_kernel(const float* __restrict__ obig,
                               float* __restrict__ om) {
    int r = blockIdx.x;                  // (b*CD + cd)*3 + d
    float s = 0.0f;
    for (int n = threadIdx.x; n < NPT; n += blockDim.x)
        s += obig[(size_t)r * NPT + n];
    __shared__ float rs[8];
    for (int o = 16; o > 0; o >>= 1) s += __shfl_xor_sync(0xffffffffu, s, o);
    if ((threadIdx.x & 31) == 0) rs[threadIdx.x >> 5] = s;
    __syncthreads();
    if (threadIdx.x == 0) {
        float t = 0.0f;
#pragma unroll
        for (int w = 0; w < 8; ++w) t += rs[w];
        om[r] = t * (1.0f / NPT);
    }
}

// ---------------------------------------------------------------------------
extern "C" void kernel_launch(void* const* d_in, const int* in_sizes, int n_in,
                              void* d_out, int out_size) {
    const float* x    = (const float*)d_in[0];
    const float* Win  = (const float*)d_in[1];
    const float* Wdin = (const float*)d_in[2];
    const float* Ws   = (const float*)d_in[3];
    const float* Wds  = (const float*)d_in[4];
    const float* Gs   = (const float*)d_in[5];
    const float* Gds  = (const float*)d_in[6];
    const float* Wout = (const float*)d_in[7];
    (void)in_sizes; (void)n_in; (void)out_size;

    float* out  = (float*)d_out;
    float* om   = out;                    // (B, CD, 3) mean
    float* obig = out + BB * CDIM * 3;    // (B, CD, 3, N)

    const int smem = 3 * 128 * 32 * 2 * 4;  // 96 KB dynamic (hi/lo slots)

    // Opt in to >48KB smem. Host-side, idempotent, graph-capture safe.
    cudaFuncSetAttribute(input_tc, cudaFuncAttributeMaxDynamicSharedMemorySize, smem);
    cudaFuncSetAttribute(lna_tc, cudaFuncAttributeMaxDynamicSharedMemorySize, smem);
    cudaFuncSetAttribute(glayer_tc, cudaFuncAttributeMaxDynamicSharedMemorySize, smem);

    knn_kernel<<<dim3(NPT / 128, BB), 128>>>(x);
    mwin_kernel<<<1, 32>>>(Win);
    input_tc<<<BB * NPT / 2, 128, smem>>>(x, Win, Wdin);

    for (int i = 0; i < LL; ++i) {
        lna_tc<<<NBLK, 128, smem>>>(Ws + i * H * H, Wds + i * H * H);
        mean_kernel<<<BB * 3 * H, 128>>>();
        gpart_kernel<<<BB, 3 * H>>>(Gs + i * H * 2 * H);
        glayer_tc<<<NBLK, 128, smem>>>(Gs + i * H * 2 * H,
                                       Gds + i * H * H,
                                       Wout, obig, i);
    }
    outmean_kernel<<<BB * CDIM * 3, 256>>>(obig, om);
}

// round 13
// speedup vs baseline: 2.5277x; 1.2288x over previous
#include <cuda_runtime.h>
#include <cuda_bf16.h>

#define BB   8
#define NPT  2048
#define KNN  16
#define H    128
#define LL   4
#define CDIM 128
#define EPS  1e-12f
#define TBLK 32                       // points per tc block
#define NBLK (BB * NPT / TBLK)        // 512 tc blocks
#define BLKF (3 * H * TBLK)           // 12288 floats per block tile [d][c][p32]

// ---------------- scratch (static device globals; no runtime alloc) --------
__device__ __align__(16) float g_bufA[NBLK * BLKF];
__device__ __align__(16) float g_bufB[NBLK * BLKF];
__device__ int   g_idx[BB * NPT * KNN];
__device__ float g_g [BB * 3 * H];
__device__ float g_gp[BB * 3 * H];
__device__ float g_M [6];            // Win^T Win (3x3 symmetric): aa,bb,cc,ab,ac,bc
__device__ float g_E [H * 3];        // Wdin @ Win  (128x3)
__device__ __align__(16) float2 g_Wsp[20 * H * H];  // pre-split weights hi/lo

// ---------------- helpers --------------------------------------------------
__device__ __forceinline__ unsigned tf32r(float f) {
    unsigned u; asm("cvt.rna.tf32.f32 %0, %1;" : "=r"(u) : "f"(f)); return u;
}
__device__ __forceinline__ float tf32f(float f) { return __uint_as_float(tf32r(f)); }
__device__ __forceinline__ float2 split32(float v) {
    float hi = tf32f(v);
    float lo = tf32f(v - hi);
    return make_float2(hi, lo);
}

__device__ __forceinline__ void mma8(float* c, const unsigned* a,
                                     unsigned b0, unsigned b1) {
    asm volatile(
        "mma.sync.aligned.m16n8k8.row.col.f32.tf32.tf32.f32 "
        "{%0,%1,%2,%3}, {%4,%5,%6,%7}, {%8,%9}, {%0,%1,%2,%3};"
        : "+f"(c[0]), "+f"(c[1]), "+f"(c[2]), "+f"(c[3])
        : "r"(a[0]), "r"(a[1]), "r"(a[2]), "r"(a[3]), "r"(b0), "r"(b1));
}

__device__ __forceinline__ void vact(float v0, float v1, float v2,
                                     float k0, float k1, float k2,
                                     float& r0, float& r1, float& r2) {
    float kn  = sqrtf(k0 * k0 + k1 * k1 + k2 * k2);
    float inv = 1.0f / fmaxf(kn, EPS);
    float a = k0 * inv, b = k1 * inv, c = k2 * inv;
    float dot = v0 * a + v1 * b + v2 * c;
    float s = fminf(dot, 0.0f);
    r0 = v0 - s * a; r1 = v1 - s * b; r2 = v2 - s * c;
}

// 3xTF32 GEMM with PRE-SPLIT A (float2 hi/lo, dense 128-stride).
// C[128h x 96col] = A * act[128c x 96col]; buf slots float2 {hi,lo},
// slot index = row*32 + (p ^ ((row&3)<<3)); warp w owns rows 32w..32w+31.
__device__ __forceinline__ void gemm3_tc(const float2* __restrict__ A,
                                         const float* __restrict__ buf,
                                         float c[2][12][4], int w, int q, int r) {
    const float2* a0p = A + (32 * w + r) * 128;
    const float2* a1p = a0p + 8 * 128;
    const float2* a2p = a0p + 16 * 128;
    const float2* a3p = a0p + 24 * 128;
    int swz = q << 3;
#pragma unroll 2
    for (int k8 = 0; k8 < 16; ++k8) {
        int kb = k8 * 8;
        float2 f00 = a0p[kb + q],     f01 = a1p[kb + q];
        float2 f02 = a0p[kb + q + 4], f03 = a1p[kb + q + 4];
        float2 f10 = a2p[kb + q],     f11 = a3p[kb + q];
        float2 f12 = a2p[kb + q + 4], f13 = a3p[kb + q + 4];
        unsigned ah[2][4], al[2][4];
        ah[0][0] = __float_as_uint(f00.x); al[0][0] = __float_as_uint(f00.y);
        ah[0][1] = __float_as_uint(f01.x); al[0][1] = __float_as_uint(f01.y);
        ah[0][2] = __float_as_uint(f02.x); al[0][2] = __float_as_uint(f02.y);
        ah[0][3] = __float_as_uint(f03.x); al[0][3] = __float_as_uint(f03.y);
        ah[1][0] = __float_as_uint(f10.x); al[1][0] = __float_as_uint(f10.y);
        ah[1][1] = __float_as_uint(f11.x); al[1][1] = __float_as_uint(f11.y);
        ah[1][2] = __float_as_uint(f12.x); al[1][2] = __float_as_uint(f12.y);
        ah[1][3] = __float_as_uint(f13.x); al[1][3] = __float_as_uint(f13.y);
#pragma unroll
        for (int jn = 0; jn < 12; ++jn) {
            int d = jn >> 2;
            int boff = (((jn & 3) * 8) ^ swz) + r;
            float2 b0 = *(const float2*)(buf + ((d * 128 + kb + q) * 32 + boff) * 2);
            float2 b1 = *(const float2*)(buf + ((d * 128 + kb + q + 4) * 32 + boff) * 2);
            unsigned bh0 = __float_as_uint(b0.x), bl0 = __float_as_uint(b0.y);
            unsigned bh1 = __float_as_uint(b1.x), bl1 = __float_as_uint(b1.y);
            mma8(c[0][jn], ah[0], bh0, bh1);
            mma8(c[1][jn], ah[1], bh0, bh1);
            mma8(c[0][jn], ah[0], bl0, bl1);
            mma8(c[1][jn], ah[1], bl0, bl1);
            mma8(c[0][jn], al[0], bh0, bh1);
            mma8(c[1][jn], al[1], bh0, bh1);
        }
    }
}

// ---------------- kNN: register-resident branch-free top-16 ----------------
__global__ __launch_bounds__(128)
void knn_kernel(const float* __restrict__ x) {
    int b = blockIdx.y;
    int i = blockIdx.x * blockDim.x + threadIdx.x;
    __shared__ float px[NPT], py[NPT], pz[NPT], sq[NPT];
    const float* xb = x + b * 3 * NPT;
    for (int n = threadIdx.x; n < NPT; n += blockDim.x) {
        float a = xb[n], c = xb[NPT + n], e = xb[2 * NPT + n];
        px[n] = a; py[n] = c; pz[n] = e;
        sq[n] = a * a + c * c + e * e;
    }
    __syncthreads();
    float qx = px[i], qy = py[i], qz = pz[i], qs = sq[i];
    float bd[KNN]; int bi[KNN];
#pragma unroll
    for (int t = 0; t < KNN; ++t) { bd[t] = 3.4e38f; bi[t] = 0; }
#pragma unroll 4
    for (int j = 0; j < NPT; ++j) {
        float dot = qx * px[j] + qy * py[j] + qz * pz[j];
        float d2  = fmaf(-2.0f, dot, qs + sq[j]);
        if (d2 < bd[KNN - 1]) {
            float cd = d2; int ci = j;
#pragma unroll
            for (int t = 0; t < KNN; ++t) {
                bool lt = cd < bd[t];
                float nd = lt ? cd    : bd[t];
                int   ni = lt ? ci    : bi[t];
                float od = lt ? bd[t] : cd;
                int   oi = lt ? bi[t] : ci;
                bd[t] = nd; bi[t] = ni;
                cd = od; ci = oi;
            }
        }
    }
    int base = (b * NPT + i) * KNN;
#pragma unroll
    for (int t = 0; t < KNN; ++t) g_idx[base + t] = bi[t];
}

// ---------------- tiny prep: M = Win^T Win, E = Wdin @ Win ------------------
__global__ void prep_small(const float* __restrict__ Win,
                           const float* __restrict__ Wdin) {
    int t = threadIdx.x;                 // 128
    float e0 = 0, e1 = 0, e2 = 0;
    for (int j = 0; j < H; ++j) {
        float wd = Wdin[t * H + j];
        e0 += wd * Win[j * 3 + 0];
        e1 += wd * Win[j * 3 + 1];
        e2 += wd * Win[j * 3 + 2];
    }
    g_E[t * 3 + 0] = e0; g_E[t * 3 + 1] = e1; g_E[t * 3 + 2] = e2;

    if (t < 32) {
        float m[6] = {0, 0, 0, 0, 0, 0};
        for (int hh = t; hh < H; hh += 32) {
            float a = Win[hh * 3], bb = Win[hh * 3 + 1], cc = Win[hh * 3 + 2];
            m[0] += a * a;  m[1] += bb * bb; m[2] += cc * cc;
            m[3] += a * bb; m[4] += a * cc;  m[5] += bb * cc;
        }
#pragma unroll
        for (int o = 16; o > 0; o >>= 1)
#pragma unroll
            for (int i = 0; i < 6; ++i)
                m[i] += __shfl_xor_sync(0xffffffffu, m[i], o);
        if (t == 0)
#pragma unroll
            for (int i = 0; i < 6; ++i) g_M[i] = m[i];
    }
}

// ---------------- pre-split weights into hi/lo float2 ----------------------
// matrix m = layer*5 + type; type: 0=Ws 1=Wds 2=Gl(local half) 3=Gds 4=WoutSlice
__global__ void presplit_kernel(const float* __restrict__ Ws,
                                const float* __restrict__ Wds,
                                const float* __restrict__ Gs,
                                const float* __restrict__ Gds,
                                const float* __restrict__ Wout) {
    int m = blockIdx.x;
    int layer = m / 5, type = m % 5;
    for (int e = threadIdx.x; e < H * H; e += blockDim.x) {
        int row = e >> 7, col = e & 127;
        float v;
        if      (type == 0) v = Ws  [layer * H * H + e];
        else if (type == 1) v = Wds [layer * H * H + e];
        else if (type == 2) v = Gs  [layer * H * 2 * H + row * 2 * H + col];
        else if (type == 3) v = Gds [layer * H * H + e];
        else                v = Wout[row * (LL * H) + layer * H + col];
        g_Wsp[m * H * H + e] = split32(v);
    }
}

// ---------------- input stage: E-matrix collapse (exact fp32) ---------------
// vec_lna(y,Win,Wdin).mean(K):  v' = (Win@y)/cn ;  kv ∝ (Wdin@Win)@y = E@y
// (k-hat is scale invariant).  cn from quadratic form y^T (Win^T Win) y.
// 8 points per block, 128 cols = 8pt x 16k; thread = channel h.
__global__ __launch_bounds__(128)
void input_pt(const float* __restrict__ x, const float* __restrict__ Win) {
    __shared__ float ysh[3][3][128];     // [ch][d][col]
    __shared__ float invcn[128];
    __shared__ float osh[3 * H][9];      // staging, padded rows
    int tid = threadIdx.x;
    int gp0 = blockIdx.x * 8;
    int b = gp0 >> 11;
    const float* xb = x + b * 3 * NPT;

    {   // phase 1: one col per thread
        int p = tid, pt = p >> 4, k = p & 15;
        int nl = (gp0 & (NPT - 1)) + pt;
        float cx = xb[nl], cy = xb[NPT + nl], cz = xb[2 * NPT + nl];
        int j = g_idx[(b * NPT + nl) * KNN + k];
        float nx = xb[j], ny = xb[NPT + j], nz = xb[2 * NPT + j];
        float nn  = sqrtf(cx * cx + cy * cy + cz * cz);
        float inv = 1.0f / fmaxf(nn, EPS);
        float dx = cx * inv, dy = cy * inv, dz = cz * inv;
        float y0[3] = {dy * nz - dz * ny, dz * nx - dx * nz, dx * ny - dy * nx};
        float y1[3] = {nx - cx, ny - cy, nz - cz};
        float y2[3] = {cx, cy, cz};
#pragma unroll
        for (int d = 0; d < 3; ++d) {
            ysh[0][d][p] = y0[d]; ysh[1][d][p] = y1[d]; ysh[2][d][p] = y2[d];
        }
        float m0 = g_M[0], m1 = g_M[1], m2 = g_M[2];
        float m3 = g_M[3], m4 = g_M[4], m5 = g_M[5];
        float s = 0.0f;
#pragma unroll
        for (int d = 0; d < 3; ++d) {
            float a = y0[d], bb = y1[d], cc = y2[d];
            s += m0 * a * a + m1 * bb * bb + m2 * cc * cc
               + 2.0f * (m3 * a * bb + m4 * a * cc + m5 * bb * cc);
        }
        invcn[p] = 1.0f / fmaxf(sqrtf(s), EPS);
    }
    __syncthreads();

    // phase 2: thread = channel h; 3-MAC matvecs via Win row + E row
    int h = tid;
    float w0 = Win[h * 3 + 0], w1 = Win[h * 3 + 1], w2 = Win[h * 3 + 2];
    float e0 = g_E[h * 3 + 0], e1 = g_E[h * 3 + 1], e2 = g_E[h * 3 + 2];
#pragma unroll 1
    for (int pt = 0; pt < 8; ++pt) {
        float a0 = 0.0f, a1 = 0.0f, a2 = 0.0f;
#pragma unroll 4
        for (int k = 0; k < 16; ++k) {
            int p = pt * 16 + k;
            float u[3], kv[3];
#pragma unroll
            for (int d = 0; d < 3; ++d) {
                float c0 = ysh[0][d][p], c1 = ysh[1][d][p], c2 = ysh[2][d][p];
                u[d]  = w0 * c0 + w1 * c1 + w2 * c2;
                kv[d] = e0 * c0 + e1 * c1 + e2 * c2;
            }
            float f  = invcn[p];
            float kn = sqrtf(kv[0] * kv[0] + kv[1] * kv[1] + kv[2] * kv[2]);
            float ki = 1.0f / fmaxf(kn, EPS);
            float k0 = kv[0] * ki, k1 = kv[1] * ki, k2 = kv[2] * ki;
            float dot = u[0] * k0 + u[1] * k1 + u[2] * k2;
            float s = fminf(dot, 0.0f);
            a0 += f * (u[0] - s * k0);
            a1 += f * (u[1] - s * k1);
            a2 += f * (u[2] - s * k2);
        }
        osh[0 * H + h][pt] = a0 * (1.0f / KNN);
        osh[1 * H + h][pt] = a1 * (1.0f / KNN);
        osh[2 * H + h][pt] = a2 * (1.0f / KNN);
    }
    __syncthreads();

    // phase 3: coalesced write into the [d][c][p32] tile
    int tb = gp0 >> 5, p0 = gp0 & 31;
    float* dst = g_bufA + (size_t)tb * BLKF;
    for (int i = tid; i < 1536; i += 128) {
        int row = i >> 2, sl = (i & 3) * 2;
        *(float2*)(dst + row * 32 + p0 + sl) =
            make_float2(osh[row][sl], osh[row][sl + 1]);
    }
}

// ---------------- lna via 3xTF32 tensor cores: bufA -> bufB -----------------
__global__ __launch_bounds__(128)
void lna_tc(int layer) {
    extern __shared__ float buf[];       // float2 hi/lo slots, 96 KB
    __shared__ float red[4][32];
    int tid = threadIdx.x;
    int w = tid >> 5, lane = tid & 31, q = lane & 3, r = lane >> 2;
    int blk = blockIdx.x;
    const float2* W2  = g_Wsp + (layer * 5 + 0) * H * H;
    const float2* Wd2 = g_Wsp + (layer * 5 + 1) * H * H;

    const float4* gsrc = (const float4*)(g_bufA + blk * BLKF);
#pragma unroll 4
    for (int i = tid; i < 3072; i += 128) {
        float4 v = gsrc[i];
        int row = i >> 3, pw = (i & 7) << 2;
        float2* ds = (float2*)buf + row * 32 + (pw ^ ((row & 3) << 3));
        ds[0] = split32(v.x); ds[1] = split32(v.y);
        ds[2] = split32(v.z); ds[3] = split32(v.w);
    }
    __syncthreads();

    float c1[2][12][4];
#pragma unroll
    for (int mt = 0; mt < 2; ++mt)
#pragma unroll
        for (int jn = 0; jn < 12; ++jn)
#pragma unroll
            for (int cr = 0; cr < 4; ++cr) c1[mt][jn][cr] = 0.0f;
    gemm3_tc(W2, buf, c1, w, q, r);

    float n2[2][4][4];
#pragma unroll
    for (int mt = 0; mt < 2; ++mt)
#pragma unroll
        for (int jj = 0; jj < 4; ++jj)
#pragma unroll
            for (int cr = 0; cr < 4; ++cr)
                n2[mt][jj][cr] = c1[mt][jj][cr] * c1[mt][jj][cr]
                               + c1[mt][4 + jj][cr] * c1[mt][4 + jj][cr]
                               + c1[mt][8 + jj][cr] * c1[mt][8 + jj][cr];
    float lcn[4][2];
#pragma unroll
    for (int jj = 0; jj < 4; ++jj)
#pragma unroll
        for (int e = 0; e < 2; ++e)
            lcn[jj][e] = n2[0][jj][e] + n2[0][jj][e + 2]
                       + n2[1][jj][e] + n2[1][jj][e + 2];
#pragma unroll
    for (int o = 4; o < 32; o <<= 1)
#pragma unroll
        for (int jj = 0; jj < 4; ++jj)
#pragma unroll
            for (int e = 0; e < 2; ++e)
                lcn[jj][e] += __shfl_xor_sync(0xffffffffu, lcn[jj][e], o);
    if (r == 0)
#pragma unroll
        for (int jj = 0; jj < 4; ++jj)
#pragma unroll
            for (int e = 0; e < 2; ++e)
                red[w][jj * 8 + 2 * q + e] = lcn[jj][e];
    __syncthreads();

    float cns[4][2];
#pragma unroll
    for (int jj = 0; jj < 4; ++jj)
#pragma unroll
        for (int e = 0; e < 2; ++e) {
            int col = jj * 8 + 2 * q + e;
            cns[jj][e] = sqrtf(red[0][col] + red[1][col] + red[2][col] + red[3][col]);
        }

#pragma unroll
    for (int mt = 0; mt < 2; ++mt)
#pragma unroll
        for (int rh = 0; rh < 2; ++rh)
#pragma unroll
            for (int jj = 0; jj < 4; ++jj) {
                int ch = 32 * w + 16 * mt + 8 * rh + r;
                int ps = (jj * 8 + 2 * q) ^ ((ch & 3) << 3);
                float nA = sqrtf(n2[mt][jj][rh * 2]);
                float nB = sqrtf(n2[mt][jj][rh * 2 + 1]);
                float f0 = (nA / fmaxf(nA, EPS)) / fmaxf(cns[jj][0], EPS);
                float f1 = (nB / fmaxf(nB, EPS)) / fmaxf(cns[jj][1], EPS);
#pragma unroll
                for (int d = 0; d < 3; ++d) {
                    float2 s0 = split32(c1[mt][4 * d + jj][rh * 2] * f0);
                    float2 s1 = split32(c1[mt][4 * d + jj][rh * 2 + 1] * f1);
                    *(float4*)((float2*)buf + (d * 128 + ch) * 32 + ps) =
                        make_float4(s0.x, s0.y, s1.x, s1.y);
                }
            }
    __syncthreads();

    float c2[2][12][4];
#pragma unroll
    for (int mt = 0; mt < 2; ++mt)
#pragma unroll
        for (int jn = 0; jn < 12; ++jn)
#pragma unroll
            for (int cr = 0; cr < 4; ++cr) c2[mt][jn][cr] = 0.0f;
    gemm3_tc(Wd2, buf, c2, w, q, r);

    float* gdst = g_bufB + blk * BLKF;
#pragma unroll
    for (int mt = 0; mt < 2; ++mt)
#pragma unroll
        for (int rh = 0; rh < 2; ++rh)
#pragma unroll
            for (int jj = 0; jj < 4; ++jj) {
                int ch = 32 * w + 16 * mt + 8 * rh + r;
                int ps = (jj * 8 + 2 * q) ^ ((ch & 3) << 3);
                float4 u0 = *(const float4*)((float2*)buf + (0 * 128 + ch) * 32 + ps);
                float4 u1 = *(const float4*)((float2*)buf + (1 * 128 + ch) * 32 + ps);
                float4 u2 = *(const float4*)((float2*)buf + (2 * 128 + ch) * 32 + ps);
                float res[3][2];
#pragma unroll
                for (int e = 0; e < 2; ++e) {
                    int cr = rh * 2 + e;
                    float v0 = e ? (u0.z + u0.w) : (u0.x + u0.y);
                    float v1 = e ? (u1.z + u1.w) : (u1.x + u1.y);
                    float v2 = e ? (u2.z + u2.w) : (u2.x + u2.y);
                    vact(v0, v1, v2,
                         c2[mt][jj][cr], c2[mt][4 + jj][cr], c2[mt][8 + jj][cr],
                         res[0][e], res[1][e], res[2][e]);
                }
#pragma unroll
                for (int d = 0; d < 3; ++d)
                    *(float2*)(gdst + (d * 128 + ch) * 32 + jj * 8 + 2 * q) =
                        make_float2(res[d][0], res[d][1]);
            }
}

// ---------------- global mean over N of bufB -> g_g ------------------------
__global__ void mean_kernel() {
    int fl = blockIdx.x;                 // b*384 + row
    int b = fl / (3 * H), row = fl - b * (3 * H);
    const float* base = g_bufB + (size_t)b * 64 * BLKF + row * 32;
    float s = 0.0f;
    for (int i = threadIdx.x; i < 512; i += 128) {
        int blk = i >> 3, p4 = (i & 7) << 2;
        float4 v = *(const float4*)(base + blk * BLKF + p4);
        s += (v.x + v.y) + (v.z + v.w);
    }
    __shared__ float rs[4];
    for (int o = 16; o > 0; o >>= 1) s += __shfl_xor_sync(0xffffffffu, s, o);
    if ((threadIdx.x & 31) == 0) rs[threadIdx.x >> 5] = s;
    __syncthreads();
    if (threadIdx.x == 0)
        g_g[fl] = (rs[0] + rs[1] + rs[2] + rs[3]) * (1.0f / NPT);
}

// ---------------- gpart = Gs[:, H:2H] @ g per batch ------------------------
__global__ void gpart_kernel(const float* __restrict__ Gi) {
    int b = blockIdx.x;
    int t = threadIdx.x;                 // 384 threads: t = d*128 + h
    __shared__ float gs[3 * H];
    gs[t] = g_g[b * 3 * H + t];
    __syncthreads();
    int d = t >> 7, h = t & 127;
    const float4* w4p = (const float4*)(Gi + h * (2 * H) + H);
    const float4* g4p = (const float4*)&gs[d * H];
    float s = 0.0f;
#pragma unroll
    for (int c = 0; c < H / 4; ++c) {
        float4 w = w4p[c], v = g4p[c];
        s += w.x * v.x + w.y * v.y + w.z * v.z + w.w * v.w;
    }
    g_gp[b * 3 * H + t] = s;
}

// -------- G-layer via 3xTF32 tensor cores + W_out accumulation -------------
__global__ __launch_bounds__(128)
void glayer_tc(float* __restrict__ obig, int layer) {
    extern __shared__ float buf[];
    __shared__ float red[4][32];
    int tid = threadIdx.x;
    int w = tid >> 5, lane = tid & 31, q = lane & 3, r = lane >> 2;
    int blk = blockIdx.x;
    int b = blk >> 6;
    int n0 = (blk & 63) * 32;
    const float2* Gl2 = g_Wsp + (layer * 5 + 2) * H * H;
    const float2* Gd2 = g_Wsp + (layer * 5 + 3) * H * H;
    const float2* Wo2 = g_Wsp + (layer * 5 + 4) * H * H;

    const float4* gsrc = (const float4*)(g_bufB + blk * BLKF);
#pragma unroll 4
    for (int i = tid; i < 3072; i += 128) {
        float4 v = gsrc[i];
        int row = i >> 3, pw = (i & 7) << 2;
        float2* ds = (float2*)buf + row * 32 + (pw ^ ((row & 3) << 3));
        ds[0] = split32(v.x); ds[1] = split32(v.y);
        ds[2] = split32(v.z); ds[3] = split32(v.w);
    }
    __syncthreads();

    float c1[2][12][4];
    float gpv[2][2][3];
#pragma unroll
    for (int mt = 0; mt < 2; ++mt)
#pragma unroll
        for (int rh = 0; rh < 2; ++rh)
#pragma unroll
            for (int d = 0; d < 3; ++d)
                gpv[mt][rh][d] =
                    g_gp[b * 3 * H + d * H + 32 * w + 16 * mt + 8 * rh + r];
#pragma unroll
    for (int mt = 0; mt < 2; ++mt)
#pragma unroll
        for (int jn = 0; jn < 12; ++jn)
#pragma unroll
            for (int cr = 0; cr < 4; ++cr)
                c1[mt][jn][cr] = gpv[mt][cr >> 1][jn >> 2];
    gemm3_tc(Gl2, buf, c1, w, q, r);

    float n2[2][4][4];
#pragma unroll
    for (int mt = 0; mt < 2; ++mt)
#pragma unroll
        for (int jj = 0; jj < 4; ++jj)
#pragma unroll
            for (int cr = 0; cr < 4; ++cr)
                n2[mt][jj][cr] = c1[mt][jj][cr] * c1[mt][jj][cr]
                               + c1[mt][4 + jj][cr] * c1[mt][4 + jj][cr]
                               + c1[mt][8 + jj][cr] * c1[mt][8 + jj][cr];
    float lcn[4][2];
#pragma unroll
    for (int jj = 0; jj < 4; ++jj)
#pragma unroll
        for (int e = 0; e < 2; ++e)
            lcn[jj][e] = n2[0][jj][e] + n2[0][jj][e + 2]
                       + n2[1][jj][e] + n2[1][jj][e + 2];
#pragma unroll
    for (int o = 4; o < 32; o <<= 1)
#pragma unroll
        for (int jj = 0; jj < 4; ++jj)
#pragma unroll
            for (int e = 0; e < 2; ++e)
                lcn[jj][e] += __shfl_xor_sync(0xffffffffu, lcn[jj][e], o);
    if (r == 0)
#pragma unroll
        for (int jj = 0; jj < 4; ++jj)
#pragma unroll
            for (int e = 0; e < 2; ++e)
                red[w][jj * 8 + 2 * q + e] = lcn[jj][e];
    __syncthreads();

    float cns[4][2];
#pragma unroll
    for (int jj = 0; jj < 4; ++jj)
#pragma unroll
        for (int e = 0; e < 2; ++e) {
            int col = jj * 8 + 2 * q + e;
            cns[jj][e] = sqrtf(red[0][col] + red[1][col] + red[2][col] + red[3][col]);
        }

#pragma unroll
    for (int mt = 0; mt < 2; ++mt)
#pragma unroll
        for (int rh = 0; rh < 2; ++rh)
#pragma unroll
            for (int jj = 0; jj < 4; ++jj) {
                int ch = 32 * w + 16 * mt + 8 * rh + r;
                int ps = (jj * 8 + 2 * q) ^ ((ch & 3) << 3);
                float nA = sqrtf(n2[mt][jj][rh * 2]);
                float nB = sqrtf(n2[mt][jj][rh * 2 + 1]);
                float f0 = (nA / fmaxf(nA, EPS)) / fmaxf(cns[jj][0], EPS);
                float f1 = (nB / fmaxf(nB, EPS)) / fmaxf(cns[jj][1], EPS);
#pragma unroll
                for (int d = 0; d < 3; ++d) {
                    float2 s0 = split32(c1[mt][4 * d + jj][rh * 2] * f0);
                    float2 s1 = split32(c1[mt][4 * d + jj][rh * 2 + 1] * f1);
                    *(float4*)((float2*)buf + (d * 128 + ch) * 32 + ps) =
                        make_float4(s0.x, s0.y, s1.x, s1.y);
                }
            }
    __syncthreads();

    float c2[2][12][4];
#pragma unroll
    for (int mt = 0; mt < 2; ++mt)
#pragma unroll
        for (int jn = 0; jn < 12; ++jn)
#pragma unroll
            for (int cr = 0; cr < 4; ++cr) c2[mt][jn][cr] = 0.0f;
    gemm3_tc(Gd2, buf, c2, w, q, r);
    __syncthreads();   // all GEMM2 reads of buf done before h2 overwrites

    float* gdst = g_bufA + blk * BLKF;
#pragma unroll
    for (int mt = 0; mt < 2; ++mt)
#pragma unroll
        for (int rh = 0; rh < 2; ++rh)
#pragma unroll
            for (int jj = 0; jj < 4; ++jj) {
                int ch = 32 * w + 16 * mt + 8 * rh + r;
                int ps = (jj * 8 + 2 * q) ^ ((ch & 3) << 3);
                float4 u0 = *(const float4*)((float2*)buf + (0 * 128 + ch) * 32 + ps);
                float4 u1 = *(const float4*)((float2*)buf + (1 * 128 + ch) * 32 + ps);
                float4 u2 = *(const float4*)((float2*)buf + (2 * 128 + ch) * 32 + ps);
                float res[3][2];
#pragma unroll
                for (int e = 0; e < 2; ++e) {
                    int cr = rh * 2 + e;
                    float v0 = e ? (u0.z + u0.w) : (u0.x + u0.y);
                    float v1 = e ? (u1.z + u1.w) : (u1.x + u1.y);
                    float v2 = e ? (u2.z + u2.w) : (u2.x + u2.y);
                    vact(v0, v1, v2,
                         c2[mt][jj][cr], c2[mt][4 + jj][cr], c2[mt][8 + jj][cr],
                         res[0][e], res[1][e], res[2][e]);
                }
#pragma unroll
                for (int d = 0; d < 3; ++d) {
                    *(float2*)(gdst + (d * 128 + ch) * 32 + jj * 8 + 2 * q) =
                        make_float2(res[d][0], res[d][1]);
                    float2 s0 = split32(res[d][0]);
                    float2 s1 = split32(res[d][1]);
                    *(float4*)((float2*)buf + (d * 128 + ch) * 32 + ps) =
                        make_float4(s0.x, s0.y, s1.x, s1.y);
                }
            }
    __syncthreads();

    float c3[2][12][4];
#pragma unroll
    for (int mt = 0; mt < 2; ++mt)
#pragma unroll
        for (int jn = 0; jn < 12; ++jn)
#pragma unroll
            for (int cr = 0; cr < 4; ++cr) c3[mt][jn][cr] = 0.0f;
    gemm3_tc(Wo2, buf, c3, w, q, r);

#pragma unroll
    for (int mt = 0; mt < 2; ++mt)
#pragma unroll
        for (int rh = 0; rh < 2; ++rh)
#pragma unroll
            for (int jj = 0; jj < 4; ++jj) {
                int ch = 32 * w + 16 * mt + 8 * rh + r;
#pragma unroll
                for (int d = 0; d < 3; ++d) {
                    float2* dp = (float2*)(obig +
                        ((size_t)(b * CDIM + ch) * 3 + d) * NPT + n0 + jj * 8 + 2 * q);
                    float v0 = c3[mt][4 * d + jj][rh * 2];
                    float v1 = c3[mt][4 * d + jj][rh * 2 + 1];
                    if (layer == 0) {
                        *dp = make_float2(v0, v1);
                    } else {
                        float2 e = *dp;
                        *dp = make_float2(e.x + v0, e.y + v1);
                    }
                }
            }
}

// ---------------- final mean over N of the big output ----------------------
__global__ void outmean_kernel(const float* __restrict__ obig,
                               float* __restrict__ om) {
    int r = blockIdx.x;                  // (b*CD + cd)*3 + d
    float s = 0.0f;
    for (int n = threadIdx.x; n < NPT; n += blockDim.x)
        s += obig[(size_t)r * NPT + n];
    __shared__ float rs[8];
    for (int o = 16; o > 0; o >>= 1) s += __shfl_xor_sync(0xffffffffu, s, o);
    if ((threadIdx.x & 31) == 0) rs[threadIdx.x >> 5] = s;
    __syncthreads();
    if (threadIdx.x == 0) {
        float t = 0.0f;
#pragma unroll
        for (int w = 0; w < 8; ++w) t += rs[w];
        om[r] = t * (1.0f / NPT);
    }
}

// ---------------------------------------------------------------------------
extern "C" void kernel_launch(void* const* d_in, const int* in_sizes, int n_in,
                              void* d_out, int out_size) {
    const float* x    = (const float*)d_in[0];
    const float* Win  = (const float*)d_in[1];
    const float* Wdin = (const float*)d_in[2];
    const float* Ws   = (const float*)d_in[3];
    const float* Wds  = (const float*)d_in[4];
    const float* Gs   = (const float*)d_in[5];
    const float* Gds  = (const float*)d_in[6];
    const float* Wout = (const float*)d_in[7];
    (void)in_sizes; (void)n_in; (void)out_size;

    float* out  = (float*)d_out;
    float* om   = out;                    // (B, CD, 3) mean
    float* obig = out + BB * CDIM * 3;    // (B, CD, 3, N)

    const int smem = 3 * 128 * 32 * 2 * 4;  // 96 KB dynamic (hi/lo slots)

    cudaFuncSetAttribute(lna_tc, cudaFuncAttributeMaxDynamicSharedMemorySize, smem);
    cudaFuncSetAttribute(glayer_tc, cudaFuncAttributeMaxDynamicSharedMemorySize, smem);

    knn_kernel<<<dim3(NPT / 128, BB), 128>>>(x);
    prep_small<<<1, 128>>>(Win, Wdin);
    presplit_kernel<<<20, 256>>>(Ws, Wds, Gs, Gds, Wout);
    input_pt<<<BB * NPT / 8, 128>>>(x, Win);

    for (int i = 0; i < LL; ++i) {
        lna_tc<<<NBLK, 128, smem>>>(i);
        mean_kernel<<<BB * 3 * H, 128>>>();
        gpart_kernel<<<BB, 3 * H>>>(Gs + i * H * 2 * H);
        glayer_tc<<<NBLK, 128, smem>>>(obig, i);
    }
    outmean_kernel<<<BB * CDIM * 3, 256>>>(obig, om);
}